// round 3
// baseline (speedup 1.0000x reference)
#include <cuda_runtime.h>
#include <cuda_fp16.h>

#define N_NODES 50000
#define NPAD    50016
#define D_EMB   64
#define N_BATCH 64
#define PB      128   // pool partial blocks

// ---------------- scratch (device globals; no allocation) ----------------
__device__ float  g_hA[NPAD * D_EMB];
__device__ float  g_hB[NPAD * D_EMB];
__device__ __half g_hhA[NPAD * D_EMB];
__device__ __half g_hhB[NPAD * D_EMB];
__device__ float  g_hnv[NPAD * D_EMB];
__device__ float  g_hsA[N_BATCH * D_EMB];
__device__ float  g_hsB[N_BATCH * D_EMB];
__device__ float  g_Wa[D_EMB * D_EMB];
__device__ float  g_Wb[D_EMB * D_EMB];
__device__ int    g_rowptr[N_NODES + 1];
__device__ float  g_pp[PB * N_BATCH * D_EMB];

// ---------------- packed f32x2 FMA (sm_103a; 2x FFMA throughput) ----------
union F2U { float2 f; unsigned long long u; };
__device__ __forceinline__ void ffma2(float2& c, float2 a, float2 b) {
    F2U A, B, C; A.f = a; B.f = b; C.f = c;
    asm("fma.rn.f32x2 %0, %1, %2, %0;" : "+l"(C.u) : "l"(A.u), "l"(B.u));
    c = C.f;
}

// ---------------- prep: fuse_w + init_h + init_hs + rowptr, one launch ----
#define INIT_BLKS ((N_NODES + 255) / 256)

__global__ void prep(const int* __restrict__ er, int nE,
                     const float* __restrict__ X, const float* __restrict__ Xs,
                     const float* __restrict__ W1, const float* __restrict__ W2,
                     const float* __restrict__ W3, const float* __restrict__ Wl,
                     float* __restrict__ h, __half* __restrict__ hh,
                     float* __restrict__ hs) {
    int b = blockIdx.x, t = threadIdx.x;
    if (b == 0) {
        // Wa = W2 @ Wl[:64], Wb = W3 @ Wl[64:]
        for (int o = t; o < 4096; o += 256) {
            int i = o >> 6, j = o & 63;
            float sa = 0.f, sb = 0.f;
            #pragma unroll 8
            for (int k = 0; k < 64; k++) {
                sa = fmaf(W2[i * 64 + k], Wl[k * 64 + j], sa);
                sb = fmaf(W3[i * 64 + k], Wl[(64 + k) * 64 + j], sb);
            }
            g_Wa[o] = sa; g_Wb[o] = sb;
        }
    } else if (b == 1) {
        // hs = l2norm(relu(Xs @ W1)), thread per batch row
        if (t < N_BATCH) {
            float x0 = Xs[t * 2], x1 = Xs[t * 2 + 1];
            float s = 0.f;
            #pragma unroll
            for (int j = 0; j < 64; j++) {
                float v = fmaxf(fmaf(x0, W1[j], x1 * W1[64 + j]), 0.f);
                s = fmaf(v, v, s);
            }
            float inv = 1.f / fmaxf(sqrtf(s), 1e-12f);
            #pragma unroll
            for (int j = 0; j < 64; j++) {
                float v = fmaxf(fmaf(x0, W1[j], x1 * W1[64 + j]), 0.f);
                hs[t * 64 + j] = v * inv;
            }
        }
    } else if (b < 2 + INIT_BLKS) {
        // h = l2norm(relu(X @ W1)), thread per node, float4 + half2 stores
        int n = (b - 2) * 256 + t;
        if (n < N_NODES) {
            float x0 = X[n * 2], x1 = X[n * 2 + 1];
            float s = 0.f;
            #pragma unroll
            for (int j = 0; j < 64; j++) {
                float v = fmaxf(fmaf(x0, W1[j], x1 * W1[64 + j]), 0.f);
                s = fmaf(v, v, s);
            }
            float inv = 1.f / fmaxf(sqrtf(s), 1e-12f);
            float4* h4 = (float4*)(h + n * 64);
            __half2* hh2 = (__half2*)(hh + n * 64);
            #pragma unroll
            for (int j = 0; j < 64; j += 4) {
                float v0 = fmaxf(fmaf(x0, W1[j],     x1 * W1[64 + j]),     0.f) * inv;
                float v1 = fmaxf(fmaf(x0, W1[j + 1], x1 * W1[64 + j + 1]), 0.f) * inv;
                float v2 = fmaxf(fmaf(x0, W1[j + 2], x1 * W1[64 + j + 2]), 0.f) * inv;
                float v3 = fmaxf(fmaf(x0, W1[j + 3], x1 * W1[64 + j + 3]), 0.f) * inv;
                h4[j / 4] = make_float4(v0, v1, v2, v3);
                hh2[j / 2]     = __floats2half2_rn(v0, v1);
                hh2[j / 2 + 1] = __floats2half2_rn(v2, v3);
            }
        }
    } else {
        // build rowptr from sorted edge_row
        int e = (b - (2 + INIT_BLKS)) * 256 + t;
        if (e < nE) {
            int r = er[e];
            int rprev = (e == 0) ? -1 : er[e - 1];
            for (int rr = rprev + 1; rr <= r; rr++) g_rowptr[rr] = e;
            if (e == nE - 1)
                for (int rr = r + 1; rr <= N_NODES; rr++) g_rowptr[rr] = nE;
        }
    }
}

// ---------------- SPMM (fp16 gather): h_nv[i] = sum h[col[e]] -------------
// warp per node; lane owns dims (2l,2l+1); 8-deep MLP for L2 latency hiding
__global__ void spmm(const __half2* __restrict__ hh, const int* __restrict__ col,
                     const int* __restrict__ rp, float2* __restrict__ out) {
    int w = (blockIdx.x * blockDim.x + threadIdx.x) >> 5;
    if (w >= N_NODES) return;
    int lane = threadIdx.x & 31;
    int s = rp[w], e = rp[w + 1];
    float ax = 0.f, ay = 0.f, bx = 0.f, by = 0.f;
    int i = s;
    for (; i + 8 <= e; i += 8) {
        int c0 = __ldg(col + i);
        int c1 = __ldg(col + i + 1);
        int c2 = __ldg(col + i + 2);
        int c3 = __ldg(col + i + 3);
        int c4 = __ldg(col + i + 4);
        int c5 = __ldg(col + i + 5);
        int c6 = __ldg(col + i + 6);
        int c7 = __ldg(col + i + 7);
        float2 v0 = __half22float2(hh[c0 * 32 + lane]);
        float2 v1 = __half22float2(hh[c1 * 32 + lane]);
        float2 v2 = __half22float2(hh[c2 * 32 + lane]);
        float2 v3 = __half22float2(hh[c3 * 32 + lane]);
        float2 v4 = __half22float2(hh[c4 * 32 + lane]);
        float2 v5 = __half22float2(hh[c5 * 32 + lane]);
        float2 v6 = __half22float2(hh[c6 * 32 + lane]);
        float2 v7 = __half22float2(hh[c7 * 32 + lane]);
        ax += (v0.x + v2.x) + (v4.x + v6.x);
        ay += (v0.y + v2.y) + (v4.y + v6.y);
        bx += (v1.x + v3.x) + (v5.x + v7.x);
        by += (v1.y + v3.y) + (v5.y + v7.y);
    }
    for (; i + 2 <= e; i += 2) {
        int c0 = __ldg(col + i);
        int c1 = __ldg(col + i + 1);
        float2 v0 = __half22float2(hh[c0 * 32 + lane]);
        float2 v1 = __half22float2(hh[c1 * 32 + lane]);
        ax += v0.x; ay += v0.y;
        bx += v1.x; by += v1.y;
    }
    if (i < e) {
        float2 v = __half22float2(hh[__ldg(col + i) * 32 + lane]);
        ax += v.x; ay += v.y;
    }
    out[w * 32 + lane] = make_float2(ax + bx, ay + by);
}

// ---------------- batch pooling stage 1 (deterministic, no atomics) -------
__global__ void __launch_bounds__(128) pool_partial(const float* __restrict__ h,
                                                    const int* __restrict__ ba, int n) {
    __shared__ float acc[2 * N_BATCH * D_EMB];  // 32 KB
    int t = threadIdx.x;
    for (int i = t; i < 2 * 4096; i += 128) acc[i] = 0.f;
    __syncthreads();
    int per = (n + PB - 1) / PB;
    int start = blockIdx.x * per;
    int end = min(start + per, n);
    int j = t & 63;
    int nl = t >> 6;
    float* my = acc + nl * 4096;
    for (int nn = start + nl; nn < end; nn += 2) {
        int b = ba[nn];
        my[b * 64 + j] += h[nn * 64 + j];
    }
    __syncthreads();
    for (int i = t; i < 4096; i += 128)
        g_pp[blockIdx.x * 4096 + i] = acc[i] + acc[4096 + i];
}

// ---------------- fused update for nodes: l2norm(relu(h@Wa+hnv@Wb+bl)) ----
__global__ void __launch_bounds__(128) update_h(
    const float* __restrict__ h, const float* __restrict__ hnv,
    const float* __restrict__ Wa, const float* __restrict__ Wb,
    const float* __restrict__ bl, float* __restrict__ out,
    __half* __restrict__ hho, int nrows) {
    __shared__ float sWa[4096], sWb[4096];
    __shared__ float sh[2048], shn[2048];
    int t = threadIdx.x;
    for (int i = t; i < 1024; i += 128) {
        ((float4*)sWa)[i] = ((const float4*)Wa)[i];
        ((float4*)sWb)[i] = ((const float4*)Wb)[i];
    }
    int base = blockIdx.x * 32;
    const float4* h4 = (const float4*)(h + base * 64);
    const float4* hn4 = (const float4*)(hnv + base * 64);
    for (int i = t; i < 512; i += 128) {
        ((float4*)sh)[i] = h4[i];
        ((float4*)shn)[i] = hn4[i];
    }
    __syncthreads();

    int nl = t >> 2, part = t & 3;
    float2 acc[8];
    #pragma unroll
    for (int i = 0; i < 8; i++) acc[i] = ((const float2*)bl)[part * 8 + i];

    const float4* wa4 = (const float4*)sWa;
    const float4* wb4 = (const float4*)sWb;
    const float* hr = sh + nl * 64;
    const float* hnr = shn + nl * 64;

    #pragma unroll 4
    for (int k = 0; k < 64; k++) {
        float a = hr[k], b = hnr[k];
        float2 a2 = make_float2(a, a), b2 = make_float2(b, b);
        #pragma unroll
        for (int i = 0; i < 4; i++) {
            float4 wa = wa4[k * 16 + part * 4 + i];
            ffma2(acc[2 * i],     a2, make_float2(wa.x, wa.y));
            ffma2(acc[2 * i + 1], a2, make_float2(wa.z, wa.w));
            float4 wb = wb4[k * 16 + part * 4 + i];
            ffma2(acc[2 * i],     b2, make_float2(wb.x, wb.y));
            ffma2(acc[2 * i + 1], b2, make_float2(wb.z, wb.w));
        }
    }

    float s = 0.f;
    #pragma unroll
    for (int i = 0; i < 8; i++) {
        acc[i].x = fmaxf(acc[i].x, 0.f);
        acc[i].y = fmaxf(acc[i].y, 0.f);
        s = fmaf(acc[i].x, acc[i].x, s);
        s = fmaf(acc[i].y, acc[i].y, s);
    }
    s += __shfl_xor_sync(0xffffffffu, s, 1);
    s += __shfl_xor_sync(0xffffffffu, s, 2);
    float inv = 1.f / fmaxf(sqrtf(s), 1e-12f);

    int n = base + nl;
    if (n < nrows) {
        float4* o4 = (float4*)(out + n * 64 + part * 16);
        union { __half2 h2[8]; uint4 u[2]; } P;
        #pragma unroll
        for (int i = 0; i < 4; i++) {
            float x0 = acc[2 * i].x * inv, y0 = acc[2 * i].y * inv;
            float x1 = acc[2 * i + 1].x * inv, y1 = acc[2 * i + 1].y * inv;
            o4[i] = make_float4(x0, y0, x1, y1);
            P.h2[2 * i]     = __floats2half2_rn(x0, y0);
            P.h2[2 * i + 1] = __floats2half2_rn(x1, y1);
        }
        uint4* ho = (uint4*)(hho + n * 64 + part * 16);
        ho[0] = P.u[0];
        ho[1] = P.u[1];
    }
}

// ---------------- fused pool-reduce + batch update ------------------------
__global__ void __launch_bounds__(128) update_hs(
    const float* __restrict__ hs, const float* __restrict__ bl,
    float* __restrict__ out) {
    __shared__ float sWa[4096], sWb[4096];
    __shared__ float sh[2048], shn[2048];
    int t = threadIdx.x;
    int base = blockIdx.x * 32;
    for (int i = t; i < 1024; i += 128) {
        ((float4*)sWa)[i] = ((const float4*)g_Wa)[i];
        ((float4*)sWb)[i] = ((const float4*)g_Wb)[i];
    }
    for (int i = t; i < 512; i += 128)
        ((float4*)sh)[i] = ((const float4*)(hs + base * 64))[i];
    // reduce PB partials for this block's 32 batch rows
    for (int i = t; i < 512; i += 128) {
        float4 s = make_float4(0.f, 0.f, 0.f, 0.f);
        #pragma unroll 4
        for (int p = 0; p < PB; p++) {
            float4 v = ((const float4*)(g_pp + p * 4096 + base * 64))[i];
            s.x += v.x; s.y += v.y; s.z += v.z; s.w += v.w;
        }
        ((float4*)shn)[i] = s;
    }
    __syncthreads();

    int nl = t >> 2, part = t & 3;
    float2 acc[8];
    #pragma unroll
    for (int i = 0; i < 8; i++) acc[i] = ((const float2*)bl)[part * 8 + i];

    const float4* wa4 = (const float4*)sWa;
    const float4* wb4 = (const float4*)sWb;
    const float* hr = sh + nl * 64;
    const float* hnr = shn + nl * 64;

    #pragma unroll 4
    for (int k = 0; k < 64; k++) {
        float a = hr[k], b = hnr[k];
        float2 a2 = make_float2(a, a), b2 = make_float2(b, b);
        #pragma unroll
        for (int i = 0; i < 4; i++) {
            float4 wa = wa4[k * 16 + part * 4 + i];
            ffma2(acc[2 * i],     a2, make_float2(wa.x, wa.y));
            ffma2(acc[2 * i + 1], a2, make_float2(wa.z, wa.w));
            float4 wb = wb4[k * 16 + part * 4 + i];
            ffma2(acc[2 * i],     b2, make_float2(wb.x, wb.y));
            ffma2(acc[2 * i + 1], b2, make_float2(wb.z, wb.w));
        }
    }

    float s = 0.f;
    #pragma unroll
    for (int i = 0; i < 8; i++) {
        acc[i].x = fmaxf(acc[i].x, 0.f);
        acc[i].y = fmaxf(acc[i].y, 0.f);
        s = fmaf(acc[i].x, acc[i].x, s);
        s = fmaf(acc[i].y, acc[i].y, s);
    }
    s += __shfl_xor_sync(0xffffffffu, s, 1);
    s += __shfl_xor_sync(0xffffffffu, s, 2);
    float inv = 1.f / fmaxf(sqrtf(s), 1e-12f);

    float4* o4 = (float4*)(out + (base + nl) * 64 + part * 16);
    #pragma unroll
    for (int i = 0; i < 4; i++)
        o4[i] = make_float4(acc[2 * i].x * inv, acc[2 * i].y * inv,
                            acc[2 * i + 1].x * inv, acc[2 * i + 1].y * inv);
}

// ---------------- host orchestration --------------------------------------
extern "C" void kernel_launch(void* const* d_in, const int* in_sizes, int n_in,
                              void* d_out, int out_size) {
    const int*   edge_row     = (const int*)d_in[0];
    const int*   edge_col     = (const int*)d_in[1];
    const int*   batch_assign = (const int*)d_in[2];
    const float* X            = (const float*)d_in[3];
    const float* Xs           = (const float*)d_in[4];
    const float* W1           = (const float*)d_in[5];
    const float* W2           = (const float*)d_in[6];
    const float* W3           = (const float*)d_in[7];
    const float* Wl           = (const float*)d_in[8];
    const float* bl           = (const float*)d_in[9];
    float* out = (float*)d_out;

    int nE = in_sizes[0];

    float *hA, *hB, *hnv, *hsA, *hsB, *Wa, *Wb;
    __half *hhA, *hhB;
    int* rp;
    cudaGetSymbolAddress((void**)&hA,  g_hA);
    cudaGetSymbolAddress((void**)&hB,  g_hB);
    cudaGetSymbolAddress((void**)&hhA, g_hhA);
    cudaGetSymbolAddress((void**)&hhB, g_hhB);
    cudaGetSymbolAddress((void**)&hnv, g_hnv);
    cudaGetSymbolAddress((void**)&hsA, g_hsA);
    cudaGetSymbolAddress((void**)&hsB, g_hsB);
    cudaGetSymbolAddress((void**)&Wa,  g_Wa);
    cudaGetSymbolAddress((void**)&Wb,  g_Wb);
    cudaGetSymbolAddress((void**)&rp,  g_rowptr);

    int prep_blocks = 2 + INIT_BLKS + (nE + 255) / 256;
    prep<<<prep_blocks, 256>>>(edge_row, nE, X, Xs, W1, W2, W3, Wl, hA, hhA, hsA);

    float* hc = hA;  float* hn_ = hB;
    __half* hhc = hhA; __half* hhn = hhB;
    float* hsc = hsA; float* hsn = hsB;
    for (int d = 0; d < 3; d++) {
        float* hout  = (d == 2) ? out : hn_;
        float* hsout = (d == 2) ? (out + N_NODES * D_EMB) : hsn;

        // spmm first: lands at launch index 5 in iter 1 -> ncu -s 5 captures it
        spmm<<<(N_NODES * 32 + 255) / 256, 256>>>((const __half2*)hhc, edge_col, rp,
                                                  (float2*)hnv);
        pool_partial<<<PB, 128>>>(hc, batch_assign, N_NODES);
        update_hs<<<2, 128>>>(hsc, bl, hsout);
        update_h<<<(N_NODES + 31) / 32, 128>>>(hc, hnv, Wa, Wb, bl, hout, hhn, N_NODES);

        float* tf = hc; hc = hn_; hn_ = tf;
        __half* th = hhc; hhc = hhn; hhn = th;
        tf = hsc; hsc = hsn; hsn = tf;
    }
}

// round 4
// speedup vs baseline: 1.1640x; 1.1640x over previous
#include <cuda_runtime.h>
#include <cuda_fp16.h>

#define N_NODES 50000
#define NPAD    50016
#define D_EMB   64
#define N_BATCH 64
#define PB      128   // pool partial blocks

// ---------------- scratch (device globals; no allocation) ----------------
__device__ float  g_hA[NPAD * D_EMB];
__device__ float  g_hB[NPAD * D_EMB];
__device__ __half g_hhA[NPAD * D_EMB];
__device__ __half g_hhB[NPAD * D_EMB];
__device__ float  g_hnv[NPAD * D_EMB];
__device__ float  g_hsA[N_BATCH * D_EMB];
__device__ float  g_hsB[N_BATCH * D_EMB];
__device__ float  g_hnvs[N_BATCH * D_EMB];
__device__ float  g_Wa[D_EMB * D_EMB];
__device__ float  g_Wb[D_EMB * D_EMB];
__device__ int    g_rowptr[N_NODES + 1];
__device__ float  g_pp[PB * N_BATCH * D_EMB];

// ---------------- packed f32x2 FMA (sm_103a; 2x FFMA throughput) ----------
union F2U { float2 f; unsigned long long u; };
__device__ __forceinline__ void ffma2(float2& c, float2 a, float2 b) {
    F2U A, B, C; A.f = a; B.f = b; C.f = c;
    asm("fma.rn.f32x2 %0, %1, %2, %0;" : "+l"(C.u) : "l"(A.u), "l"(B.u));
    c = C.f;
}

// ---------------- prep: fuse_w + init_h + init_hs + rowptr, one launch ----
#define INIT_BLKS ((N_NODES + 255) / 256)

__global__ void prep(const int* __restrict__ er, int nE,
                     const float* __restrict__ X, const float* __restrict__ Xs,
                     const float* __restrict__ W1, const float* __restrict__ W2,
                     const float* __restrict__ W3, const float* __restrict__ Wl,
                     float* __restrict__ h, __half* __restrict__ hh,
                     float* __restrict__ hs) {
    int b = blockIdx.x, t = threadIdx.x;
    if (b == 0) {
        // Wa = W2 @ Wl[:64], Wb = W3 @ Wl[64:]
        for (int o = t; o < 4096; o += 256) {
            int i = o >> 6, j = o & 63;
            float sa = 0.f, sb = 0.f;
            #pragma unroll 8
            for (int k = 0; k < 64; k++) {
                sa = fmaf(W2[i * 64 + k], Wl[k * 64 + j], sa);
                sb = fmaf(W3[i * 64 + k], Wl[(64 + k) * 64 + j], sb);
            }
            g_Wa[o] = sa; g_Wb[o] = sb;
        }
    } else if (b == 1) {
        // hs = l2norm(relu(Xs @ W1)), thread per batch row
        if (t < N_BATCH) {
            float x0 = Xs[t * 2], x1 = Xs[t * 2 + 1];
            float s = 0.f;
            #pragma unroll
            for (int j = 0; j < 64; j++) {
                float v = fmaxf(fmaf(x0, W1[j], x1 * W1[64 + j]), 0.f);
                s = fmaf(v, v, s);
            }
            float inv = 1.f / fmaxf(sqrtf(s), 1e-12f);
            #pragma unroll
            for (int j = 0; j < 64; j++) {
                float v = fmaxf(fmaf(x0, W1[j], x1 * W1[64 + j]), 0.f);
                hs[t * 64 + j] = v * inv;
            }
        }
    } else if (b < 2 + INIT_BLKS) {
        // h = l2norm(relu(X @ W1)), thread per node, float4 + half2 stores
        int n = (b - 2) * 256 + t;
        if (n < N_NODES) {
            float x0 = X[n * 2], x1 = X[n * 2 + 1];
            float s = 0.f;
            #pragma unroll
            for (int j = 0; j < 64; j++) {
                float v = fmaxf(fmaf(x0, W1[j], x1 * W1[64 + j]), 0.f);
                s = fmaf(v, v, s);
            }
            float inv = 1.f / fmaxf(sqrtf(s), 1e-12f);
            float4* h4 = (float4*)(h + n * 64);
            __half2* hh2 = (__half2*)(hh + n * 64);
            #pragma unroll
            for (int j = 0; j < 64; j += 4) {
                float v0 = fmaxf(fmaf(x0, W1[j],     x1 * W1[64 + j]),     0.f) * inv;
                float v1 = fmaxf(fmaf(x0, W1[j + 1], x1 * W1[64 + j + 1]), 0.f) * inv;
                float v2 = fmaxf(fmaf(x0, W1[j + 2], x1 * W1[64 + j + 2]), 0.f) * inv;
                float v3 = fmaxf(fmaf(x0, W1[j + 3], x1 * W1[64 + j + 3]), 0.f) * inv;
                h4[j / 4] = make_float4(v0, v1, v2, v3);
                hh2[j / 2]     = __floats2half2_rn(v0, v1);
                hh2[j / 2 + 1] = __floats2half2_rn(v2, v3);
            }
        }
    } else {
        // build rowptr from sorted edge_row
        int e = (b - (2 + INIT_BLKS)) * 256 + t;
        if (e < nE) {
            int r = er[e];
            int rprev = (e == 0) ? -1 : er[e - 1];
            for (int rr = rprev + 1; rr <= r; rr++) g_rowptr[rr] = e;
            if (e == nE - 1)
                for (int rr = r + 1; rr <= N_NODES; rr++) g_rowptr[rr] = nE;
        }
    }
}

// ---------------- SPMM (fp16 gather): h_nv[i] = sum h[col[e]] -------------
// warp per node; lane owns dims (2l,2l+1); 8-deep MLP for L2 latency hiding
__global__ void spmm(const __half2* __restrict__ hh, const int* __restrict__ col,
                     const int* __restrict__ rp, float2* __restrict__ out) {
    int w = (blockIdx.x * blockDim.x + threadIdx.x) >> 5;
    if (w >= N_NODES) return;
    int lane = threadIdx.x & 31;
    int s = rp[w], e = rp[w + 1];
    float ax = 0.f, ay = 0.f, bx = 0.f, by = 0.f;
    int i = s;
    for (; i + 8 <= e; i += 8) {
        int c0 = __ldg(col + i);
        int c1 = __ldg(col + i + 1);
        int c2 = __ldg(col + i + 2);
        int c3 = __ldg(col + i + 3);
        int c4 = __ldg(col + i + 4);
        int c5 = __ldg(col + i + 5);
        int c6 = __ldg(col + i + 6);
        int c7 = __ldg(col + i + 7);
        float2 v0 = __half22float2(hh[c0 * 32 + lane]);
        float2 v1 = __half22float2(hh[c1 * 32 + lane]);
        float2 v2 = __half22float2(hh[c2 * 32 + lane]);
        float2 v3 = __half22float2(hh[c3 * 32 + lane]);
        float2 v4 = __half22float2(hh[c4 * 32 + lane]);
        float2 v5 = __half22float2(hh[c5 * 32 + lane]);
        float2 v6 = __half22float2(hh[c6 * 32 + lane]);
        float2 v7 = __half22float2(hh[c7 * 32 + lane]);
        ax += (v0.x + v2.x) + (v4.x + v6.x);
        ay += (v0.y + v2.y) + (v4.y + v6.y);
        bx += (v1.x + v3.x) + (v5.x + v7.x);
        by += (v1.y + v3.y) + (v5.y + v7.y);
    }
    for (; i + 2 <= e; i += 2) {
        int c0 = __ldg(col + i);
        int c1 = __ldg(col + i + 1);
        float2 v0 = __half22float2(hh[c0 * 32 + lane]);
        float2 v1 = __half22float2(hh[c1 * 32 + lane]);
        ax += v0.x; ay += v0.y;
        bx += v1.x; by += v1.y;
    }
    if (i < e) {
        float2 v = __half22float2(hh[__ldg(col + i) * 32 + lane]);
        ax += v.x; ay += v.y;
    }
    out[w * 32 + lane] = make_float2(ax + bx, ay + by);
}

// ---------------- batch pooling stage 1 (deterministic, no atomics) -------
__global__ void __launch_bounds__(128) pool_partial(const float* __restrict__ h,
                                                    const int* __restrict__ ba, int n) {
    __shared__ float acc[2 * N_BATCH * D_EMB];  // 32 KB
    int t = threadIdx.x;
    for (int i = t; i < 2 * 4096; i += 128) acc[i] = 0.f;
    __syncthreads();
    int per = (n + PB - 1) / PB;
    int start = blockIdx.x * per;
    int end = min(start + per, n);
    int j = t & 63;
    int nl = t >> 6;
    float* my = acc + nl * 4096;
    for (int nn = start + nl; nn < end; nn += 2) {
        int b = ba[nn];
        my[b * 64 + j] += h[nn * 64 + j];
    }
    __syncthreads();
    for (int i = t; i < 4096; i += 128)
        g_pp[blockIdx.x * 4096 + i] = acc[i] + acc[4096 + i];
}

// ---------------- pooling stage 2: wide reduce (4096 threads) -------------
__global__ void pool_reduce(float* __restrict__ out) {
    int i = blockIdx.x * blockDim.x + threadIdx.x;  // 4096 threads
    float s = 0.f;
    #pragma unroll 8
    for (int b = 0; b < PB; b++) s += g_pp[b * 4096 + i];
    out[i] = s;
}

// ---------------- fused update for nodes: l2norm(relu(h@Wa+hnv@Wb+bl)) ----
__global__ void __launch_bounds__(128) update_h(
    const float* __restrict__ h, const float* __restrict__ hnv,
    const float* __restrict__ Wa, const float* __restrict__ Wb,
    const float* __restrict__ bl, float* __restrict__ out,
    __half* __restrict__ hho, int nrows) {
    __shared__ float sWa[4096], sWb[4096];
    __shared__ float sh[2048], shn[2048];
    int t = threadIdx.x;
    for (int i = t; i < 1024; i += 128) {
        ((float4*)sWa)[i] = ((const float4*)Wa)[i];
        ((float4*)sWb)[i] = ((const float4*)Wb)[i];
    }
    int base = blockIdx.x * 32;
    const float4* h4 = (const float4*)(h + base * 64);
    const float4* hn4 = (const float4*)(hnv + base * 64);
    for (int i = t; i < 512; i += 128) {
        ((float4*)sh)[i] = h4[i];
        ((float4*)shn)[i] = hn4[i];
    }
    __syncthreads();

    int nl = t >> 2, part = t & 3;
    float2 acc[8];
    #pragma unroll
    for (int i = 0; i < 8; i++) acc[i] = ((const float2*)bl)[part * 8 + i];

    const float4* wa4 = (const float4*)sWa;
    const float4* wb4 = (const float4*)sWb;
    const float* hr = sh + nl * 64;
    const float* hnr = shn + nl * 64;

    #pragma unroll 4
    for (int k = 0; k < 64; k++) {
        float a = hr[k], b = hnr[k];
        float2 a2 = make_float2(a, a), b2 = make_float2(b, b);
        #pragma unroll
        for (int i = 0; i < 4; i++) {
            float4 wa = wa4[k * 16 + part * 4 + i];
            ffma2(acc[2 * i],     a2, make_float2(wa.x, wa.y));
            ffma2(acc[2 * i + 1], a2, make_float2(wa.z, wa.w));
            float4 wb = wb4[k * 16 + part * 4 + i];
            ffma2(acc[2 * i],     b2, make_float2(wb.x, wb.y));
            ffma2(acc[2 * i + 1], b2, make_float2(wb.z, wb.w));
        }
    }

    float s = 0.f;
    #pragma unroll
    for (int i = 0; i < 8; i++) {
        acc[i].x = fmaxf(acc[i].x, 0.f);
        acc[i].y = fmaxf(acc[i].y, 0.f);
        s = fmaf(acc[i].x, acc[i].x, s);
        s = fmaf(acc[i].y, acc[i].y, s);
    }
    s += __shfl_xor_sync(0xffffffffu, s, 1);
    s += __shfl_xor_sync(0xffffffffu, s, 2);
    float inv = 1.f / fmaxf(sqrtf(s), 1e-12f);

    int n = base + nl;
    if (n < nrows) {
        float4* o4 = (float4*)(out + n * 64 + part * 16);
        union { __half2 h2[8]; uint4 u[2]; } P;
        #pragma unroll
        for (int i = 0; i < 4; i++) {
            float x0 = acc[2 * i].x * inv, y0 = acc[2 * i].y * inv;
            float x1 = acc[2 * i + 1].x * inv, y1 = acc[2 * i + 1].y * inv;
            o4[i] = make_float4(x0, y0, x1, y1);
            P.h2[2 * i]     = __floats2half2_rn(x0, y0);
            P.h2[2 * i + 1] = __floats2half2_rn(x1, y1);
        }
        uint4* ho = (uint4*)(hho + n * 64 + part * 16);
        ho[0] = P.u[0];
        ho[1] = P.u[1];
    }
}

// ---------------- batch update (reads reduced hnvs) -----------------------
__global__ void __launch_bounds__(128) update_hs(
    const float* __restrict__ hs, const float* __restrict__ hnvs,
    const float* __restrict__ bl, float* __restrict__ out) {
    __shared__ float sWa[4096], sWb[4096];
    __shared__ float sh[2048], shn[2048];
    int t = threadIdx.x;
    int base = blockIdx.x * 32;
    for (int i = t; i < 1024; i += 128) {
        ((float4*)sWa)[i] = ((const float4*)g_Wa)[i];
        ((float4*)sWb)[i] = ((const float4*)g_Wb)[i];
    }
    for (int i = t; i < 512; i += 128) {
        ((float4*)sh)[i]  = ((const float4*)(hs + base * 64))[i];
        ((float4*)shn)[i] = ((const float4*)(hnvs + base * 64))[i];
    }
    __syncthreads();

    int nl = t >> 2, part = t & 3;
    float2 acc[8];
    #pragma unroll
    for (int i = 0; i < 8; i++) acc[i] = ((const float2*)bl)[part * 8 + i];

    const float4* wa4 = (const float4*)sWa;
    const float4* wb4 = (const float4*)sWb;
    const float* hr = sh + nl * 64;
    const float* hnr = shn + nl * 64;

    #pragma unroll 4
    for (int k = 0; k < 64; k++) {
        float a = hr[k], b = hnr[k];
        float2 a2 = make_float2(a, a), b2 = make_float2(b, b);
        #pragma unroll
        for (int i = 0; i < 4; i++) {
            float4 wa = wa4[k * 16 + part * 4 + i];
            ffma2(acc[2 * i],     a2, make_float2(wa.x, wa.y));
            ffma2(acc[2 * i + 1], a2, make_float2(wa.z, wa.w));
            float4 wb = wb4[k * 16 + part * 4 + i];
            ffma2(acc[2 * i],     b2, make_float2(wb.x, wb.y));
            ffma2(acc[2 * i + 1], b2, make_float2(wb.z, wb.w));
        }
    }

    float s = 0.f;
    #pragma unroll
    for (int i = 0; i < 8; i++) {
        acc[i].x = fmaxf(acc[i].x, 0.f);
        acc[i].y = fmaxf(acc[i].y, 0.f);
        s = fmaf(acc[i].x, acc[i].x, s);
        s = fmaf(acc[i].y, acc[i].y, s);
    }
    s += __shfl_xor_sync(0xffffffffu, s, 1);
    s += __shfl_xor_sync(0xffffffffu, s, 2);
    float inv = 1.f / fmaxf(sqrtf(s), 1e-12f);

    float4* o4 = (float4*)(out + (base + nl) * 64 + part * 16);
    #pragma unroll
    for (int i = 0; i < 4; i++)
        o4[i] = make_float4(acc[2 * i].x * inv, acc[2 * i].y * inv,
                            acc[2 * i + 1].x * inv, acc[2 * i + 1].y * inv);
}

// ---------------- host orchestration --------------------------------------
extern "C" void kernel_launch(void* const* d_in, const int* in_sizes, int n_in,
                              void* d_out, int out_size) {
    const int*   edge_row     = (const int*)d_in[0];
    const int*   edge_col     = (const int*)d_in[1];
    const int*   batch_assign = (const int*)d_in[2];
    const float* X            = (const float*)d_in[3];
    const float* Xs           = (const float*)d_in[4];
    const float* W1           = (const float*)d_in[5];
    const float* W2           = (const float*)d_in[6];
    const float* W3           = (const float*)d_in[7];
    const float* Wl           = (const float*)d_in[8];
    const float* bl           = (const float*)d_in[9];
    float* out = (float*)d_out;

    int nE = in_sizes[0];

    float *hA, *hB, *hnv, *hsA, *hsB, *hnvs, *Wa, *Wb;
    __half *hhA, *hhB;
    int* rp;
    cudaGetSymbolAddress((void**)&hA,   g_hA);
    cudaGetSymbolAddress((void**)&hB,   g_hB);
    cudaGetSymbolAddress((void**)&hhA,  g_hhA);
    cudaGetSymbolAddress((void**)&hhB,  g_hhB);
    cudaGetSymbolAddress((void**)&hnv,  g_hnv);
    cudaGetSymbolAddress((void**)&hsA,  g_hsA);
    cudaGetSymbolAddress((void**)&hsB,  g_hsB);
    cudaGetSymbolAddress((void**)&hnvs, g_hnvs);
    cudaGetSymbolAddress((void**)&Wa,   g_Wa);
    cudaGetSymbolAddress((void**)&Wb,   g_Wb);
    cudaGetSymbolAddress((void**)&rp,   g_rowptr);

    int prep_blocks = 2 + INIT_BLKS + (nE + 255) / 256;
    prep<<<prep_blocks, 256>>>(edge_row, nE, X, Xs, W1, W2, W3, Wl, hA, hhA, hsA);

    float* hc = hA;  float* hn_ = hB;
    __half* hhc = hhA; __half* hhn = hhB;
    float* hsc = hsA; float* hsn = hsB;
    for (int d = 0; d < 3; d++) {
        float* hout  = (d == 2) ? out : hn_;
        float* hsout = (d == 2) ? (out + N_NODES * D_EMB) : hsn;

        spmm<<<(N_NODES * 32 + 255) / 256, 256>>>((const __half2*)hhc, edge_col, rp,
                                                  (float2*)hnv);
        pool_partial<<<PB, 128>>>(hc, batch_assign, N_NODES);
        pool_reduce<<<16, 256>>>(hnvs);
        update_hs<<<2, 128>>>(hsc, hnvs, bl, hsout);
        update_h<<<(N_NODES + 31) / 32, 128>>>(hc, hnv, Wa, Wb, bl, hout, hhn, N_NODES);

        float* tf = hc; hc = hn_; hn_ = tf;
        __half* th = hhc; hhc = hhn; hhn = th;
        tf = hsc; hsc = hsn; hsn = tf;
    }
}

// round 5
// speedup vs baseline: 1.4659x; 1.2594x over previous
#include <cuda_runtime.h>
#include <cuda_fp16.h>

#define N_NODES 50000
#define NPAD    50016
#define D_EMB   64
#define N_BATCH 64
#define PB      128   // pool partial blocks

// ---------------- scratch (device globals; no allocation) ----------------
__device__ float  g_hA[NPAD * D_EMB];
__device__ float  g_hB[NPAD * D_EMB];
__device__ __half g_hhA[NPAD * D_EMB];
__device__ __half g_hhB[NPAD * D_EMB];
__device__ float  g_hnv[NPAD * D_EMB];
__device__ float  g_hsA[N_BATCH * D_EMB];
__device__ float  g_hsB[N_BATCH * D_EMB];
__device__ float  g_Wa[D_EMB * D_EMB];
__device__ float  g_Wb[D_EMB * D_EMB];
__device__ int    g_rowptr[N_NODES + 1];
__device__ float  g_pp[PB * N_BATCH * D_EMB];
__device__ float  g_ppq[4 * N_BATCH * D_EMB];   // 4 quarter-reduced partials

// ---------------- packed f32x2 FMA (sm_103a; 2x FFMA throughput) ----------
union F2U { float2 f; unsigned long long u; };
__device__ __forceinline__ void ffma2(float2& c, float2 a, float2 b) {
    F2U A, B, C; A.f = a; B.f = b; C.f = c;
    asm("fma.rn.f32x2 %0, %1, %2, %0;" : "+l"(C.u) : "l"(A.u), "l"(B.u));
    c = C.f;
}

// ---------------- prep: fuse_w + init_h + init_hs + rowptr, one launch ----
#define INIT_BLKS ((N_NODES + 255) / 256)

__global__ void prep(const int* __restrict__ er, int nE,
                     const float* __restrict__ X, const float* __restrict__ Xs,
                     const float* __restrict__ W1, const float* __restrict__ W2,
                     const float* __restrict__ W3, const float* __restrict__ Wl,
                     float* __restrict__ h, __half* __restrict__ hh,
                     float* __restrict__ hs) {
    int b = blockIdx.x, t = threadIdx.x;
    if (b == 0) {
        for (int o = t; o < 4096; o += 256) {
            int i = o >> 6, j = o & 63;
            float sa = 0.f, sb = 0.f;
            #pragma unroll 8
            for (int k = 0; k < 64; k++) {
                sa = fmaf(W2[i * 64 + k], Wl[k * 64 + j], sa);
                sb = fmaf(W3[i * 64 + k], Wl[(64 + k) * 64 + j], sb);
            }
            g_Wa[o] = sa; g_Wb[o] = sb;
        }
    } else if (b == 1) {
        if (t < N_BATCH) {
            float x0 = Xs[t * 2], x1 = Xs[t * 2 + 1];
            float s = 0.f;
            #pragma unroll
            for (int j = 0; j < 64; j++) {
                float v = fmaxf(fmaf(x0, W1[j], x1 * W1[64 + j]), 0.f);
                s = fmaf(v, v, s);
            }
            float inv = 1.f / fmaxf(sqrtf(s), 1e-12f);
            #pragma unroll
            for (int j = 0; j < 64; j++) {
                float v = fmaxf(fmaf(x0, W1[j], x1 * W1[64 + j]), 0.f);
                hs[t * 64 + j] = v * inv;
            }
        }
    } else if (b < 2 + INIT_BLKS) {
        int n = (b - 2) * 256 + t;
        if (n < N_NODES) {
            float x0 = X[n * 2], x1 = X[n * 2 + 1];
            float s = 0.f;
            #pragma unroll
            for (int j = 0; j < 64; j++) {
                float v = fmaxf(fmaf(x0, W1[j], x1 * W1[64 + j]), 0.f);
                s = fmaf(v, v, s);
            }
            float inv = 1.f / fmaxf(sqrtf(s), 1e-12f);
            float4* h4 = (float4*)(h + n * 64);
            __half2* hh2 = (__half2*)(hh + n * 64);
            #pragma unroll
            for (int j = 0; j < 64; j += 4) {
                float v0 = fmaxf(fmaf(x0, W1[j],     x1 * W1[64 + j]),     0.f) * inv;
                float v1 = fmaxf(fmaf(x0, W1[j + 1], x1 * W1[64 + j + 1]), 0.f) * inv;
                float v2 = fmaxf(fmaf(x0, W1[j + 2], x1 * W1[64 + j + 2]), 0.f) * inv;
                float v3 = fmaxf(fmaf(x0, W1[j + 3], x1 * W1[64 + j + 3]), 0.f) * inv;
                h4[j / 4] = make_float4(v0, v1, v2, v3);
                hh2[j / 2]     = __floats2half2_rn(v0, v1);
                hh2[j / 2 + 1] = __floats2half2_rn(v2, v3);
            }
        }
    } else {
        int e = (b - (2 + INIT_BLKS)) * 256 + t;
        if (e < nE) {
            int r = er[e];
            int rprev = (e == 0) ? -1 : er[e - 1];
            for (int rr = rprev + 1; rr <= r; rr++) g_rowptr[rr] = e;
            if (e == nE - 1)
                for (int rr = r + 1; rr <= N_NODES; rr++) g_rowptr[rr] = nE;
        }
    }
}

// ---------------- SPMM (fp16 gather, 16-deep MLP) -------------------------
__global__ void spmm(const __half2* __restrict__ hh, const int* __restrict__ col,
                     const int* __restrict__ rp, float2* __restrict__ out) {
    int w = (blockIdx.x * blockDim.x + threadIdx.x) >> 5;
    if (w >= N_NODES) return;
    int lane = threadIdx.x & 31;
    int s = rp[w], e = rp[w + 1];
    float ax = 0.f, ay = 0.f, bx = 0.f, by = 0.f;
    int i = s;
    for (; i + 16 <= e; i += 16) {
        int c[16];
        #pragma unroll
        for (int u = 0; u < 16; u++) c[u] = __ldg(col + i + u);
        float2 v[16];
        #pragma unroll
        for (int u = 0; u < 16; u++) v[u] = __half22float2(hh[c[u] * 32 + lane]);
        #pragma unroll
        for (int u = 0; u < 16; u += 2) {
            ax += v[u].x;     ay += v[u].y;
            bx += v[u + 1].x; by += v[u + 1].y;
        }
    }
    for (; i + 4 <= e; i += 4) {
        int c0 = __ldg(col + i);
        int c1 = __ldg(col + i + 1);
        int c2 = __ldg(col + i + 2);
        int c3 = __ldg(col + i + 3);
        float2 v0 = __half22float2(hh[c0 * 32 + lane]);
        float2 v1 = __half22float2(hh[c1 * 32 + lane]);
        float2 v2 = __half22float2(hh[c2 * 32 + lane]);
        float2 v3 = __half22float2(hh[c3 * 32 + lane]);
        ax += v0.x + v2.x; ay += v0.y + v2.y;
        bx += v1.x + v3.x; by += v1.y + v3.y;
    }
    for (; i < e; i++) {
        float2 v = __half22float2(hh[__ldg(col + i) * 32 + lane]);
        ax += v.x; ay += v.y;
    }
    out[w * 32 + lane] = make_float2(ax + bx, ay + by);
}

// ---------------- batch pooling stage 1 (deterministic, no atomics) -------
__global__ void __launch_bounds__(128) pool_partial(const float* __restrict__ h,
                                                    const int* __restrict__ ba, int n) {
    __shared__ float acc[2 * N_BATCH * D_EMB];  // 32 KB
    int t = threadIdx.x;
    for (int i = t; i < 2 * 4096; i += 128) acc[i] = 0.f;
    __syncthreads();
    int per = (n + PB - 1) / PB;
    int start = blockIdx.x * per;
    int end = min(start + per, n);
    int j = t & 63;
    int nl = t >> 6;
    float* my = acc + nl * 4096;
    for (int nn = start + nl; nn < end; nn += 2) {
        int b = ba[nn];
        my[b * 64 + j] += h[nn * 64 + j];
    }
    __syncthreads();
    for (int i = t; i < 4096; i += 128)
        g_pp[blockIdx.x * 4096 + i] = acc[i] + acc[4096 + i];
}

// ---------------- pooling stage 2: 4096 threads, float4, 4-way K-split ----
__global__ void pool_reduce() {
    int tid = blockIdx.x * blockDim.x + threadIdx.x;  // 4096
    int q = tid >> 10, i4 = tid & 1023;
    const float4* pp = (const float4*)g_pp;
    float4 s = make_float4(0.f, 0.f, 0.f, 0.f);
    #pragma unroll 8
    for (int b = q * 32; b < q * 32 + 32; b++) {
        float4 v = pp[b * 1024 + i4];
        s.x += v.x; s.y += v.y; s.z += v.z; s.w += v.w;
    }
    ((float4*)g_ppq)[q * 1024 + i4] = s;
}

// ---------------- fused update for nodes ----------------------------------
__global__ void __launch_bounds__(128) update_h(
    const float* __restrict__ h, const float* __restrict__ hnv,
    const float* __restrict__ Wa, const float* __restrict__ Wb,
    const float* __restrict__ bl, float* __restrict__ out,
    __half* __restrict__ hho, int nrows) {
    __shared__ float sWa[4096], sWb[4096];
    __shared__ float sh[2048], shn[2048];
    int t = threadIdx.x;
    for (int i = t; i < 1024; i += 128) {
        ((float4*)sWa)[i] = ((const float4*)Wa)[i];
        ((float4*)sWb)[i] = ((const float4*)Wb)[i];
    }
    int base = blockIdx.x * 32;
    const float4* h4 = (const float4*)(h + base * 64);
    const float4* hn4 = (const float4*)(hnv + base * 64);
    for (int i = t; i < 512; i += 128) {
        ((float4*)sh)[i] = h4[i];
        ((float4*)shn)[i] = hn4[i];
    }
    __syncthreads();

    int nl = t >> 2, part = t & 3;
    float2 acc[8];
    #pragma unroll
    for (int i = 0; i < 8; i++) acc[i] = ((const float2*)bl)[part * 8 + i];

    const float4* wa4 = (const float4*)sWa;
    const float4* wb4 = (const float4*)sWb;
    const float* hr = sh + nl * 64;
    const float* hnr = shn + nl * 64;

    #pragma unroll 4
    for (int k = 0; k < 64; k++) {
        float a = hr[k], b = hnr[k];
        float2 a2 = make_float2(a, a), b2 = make_float2(b, b);
        #pragma unroll
        for (int i = 0; i < 4; i++) {
            float4 wa = wa4[k * 16 + part * 4 + i];
            ffma2(acc[2 * i],     a2, make_float2(wa.x, wa.y));
            ffma2(acc[2 * i + 1], a2, make_float2(wa.z, wa.w));
            float4 wb = wb4[k * 16 + part * 4 + i];
            ffma2(acc[2 * i],     b2, make_float2(wb.x, wb.y));
            ffma2(acc[2 * i + 1], b2, make_float2(wb.z, wb.w));
        }
    }

    float s = 0.f;
    #pragma unroll
    for (int i = 0; i < 8; i++) {
        acc[i].x = fmaxf(acc[i].x, 0.f);
        acc[i].y = fmaxf(acc[i].y, 0.f);
        s = fmaf(acc[i].x, acc[i].x, s);
        s = fmaf(acc[i].y, acc[i].y, s);
    }
    s += __shfl_xor_sync(0xffffffffu, s, 1);
    s += __shfl_xor_sync(0xffffffffu, s, 2);
    float inv = 1.f / fmaxf(sqrtf(s), 1e-12f);

    int n = base + nl;
    if (n < nrows) {
        float4* o4 = (float4*)(out + n * 64 + part * 16);
        union { __half2 h2[8]; uint4 u[2]; } P;
        #pragma unroll
        for (int i = 0; i < 4; i++) {
            float x0 = acc[2 * i].x * inv, y0 = acc[2 * i].y * inv;
            float x1 = acc[2 * i + 1].x * inv, y1 = acc[2 * i + 1].y * inv;
            o4[i] = make_float4(x0, y0, x1, y1);
            P.h2[2 * i]     = __floats2half2_rn(x0, y0);
            P.h2[2 * i + 1] = __floats2half2_rn(x1, y1);
        }
        uint4* ho = (uint4*)(hho + n * 64 + part * 16);
        ho[0] = P.u[0];
        ho[1] = P.u[1];
    }
}

// ---------------- batch update (folds 4-quarter reduce) -------------------
__global__ void __launch_bounds__(128) update_hs(
    const float* __restrict__ hs, const float* __restrict__ bl,
    float* __restrict__ out) {
    __shared__ float sWa[4096], sWb[4096];
    __shared__ float sh[2048], shn[2048];
    int t = threadIdx.x;
    int base = blockIdx.x * 32;
    for (int i = t; i < 1024; i += 128) {
        ((float4*)sWa)[i] = ((const float4*)g_Wa)[i];
        ((float4*)sWb)[i] = ((const float4*)g_Wb)[i];
    }
    for (int i = t; i < 512; i += 128)
        ((float4*)sh)[i] = ((const float4*)(hs + base * 64))[i];
    for (int i = t; i < 512; i += 128) {
        float4 s = make_float4(0.f, 0.f, 0.f, 0.f);
        #pragma unroll
        for (int q = 0; q < 4; q++) {
            float4 v = ((const float4*)g_ppq)[q * 1024 + base * 16 + i];
            s.x += v.x; s.y += v.y; s.z += v.z; s.w += v.w;
        }
        ((float4*)shn)[i] = s;
    }
    __syncthreads();

    int nl = t >> 2, part = t & 3;
    float2 acc[8];
    #pragma unroll
    for (int i = 0; i < 8; i++) acc[i] = ((const float2*)bl)[part * 8 + i];

    const float4* wa4 = (const float4*)sWa;
    const float4* wb4 = (const float4*)sWb;
    const float* hr = sh + nl * 64;
    const float* hnr = shn + nl * 64;

    #pragma unroll 4
    for (int k = 0; k < 64; k++) {
        float a = hr[k], b = hnr[k];
        float2 a2 = make_float2(a, a), b2 = make_float2(b, b);
        #pragma unroll
        for (int i = 0; i < 4; i++) {
            float4 wa = wa4[k * 16 + part * 4 + i];
            ffma2(acc[2 * i],     a2, make_float2(wa.x, wa.y));
            ffma2(acc[2 * i + 1], a2, make_float2(wa.z, wa.w));
            float4 wb = wb4[k * 16 + part * 4 + i];
            ffma2(acc[2 * i],     b2, make_float2(wb.x, wb.y));
            ffma2(acc[2 * i + 1], b2, make_float2(wb.z, wb.w));
        }
    }

    float s = 0.f;
    #pragma unroll
    for (int i = 0; i < 8; i++) {
        acc[i].x = fmaxf(acc[i].x, 0.f);
        acc[i].y = fmaxf(acc[i].y, 0.f);
        s = fmaf(acc[i].x, acc[i].x, s);
        s = fmaf(acc[i].y, acc[i].y, s);
    }
    s += __shfl_xor_sync(0xffffffffu, s, 1);
    s += __shfl_xor_sync(0xffffffffu, s, 2);
    float inv = 1.f / fmaxf(sqrtf(s), 1e-12f);

    float4* o4 = (float4*)(out + (base + nl) * 64 + part * 16);
    #pragma unroll
    for (int i = 0; i < 4; i++)
        o4[i] = make_float4(acc[2 * i].x * inv, acc[2 * i].y * inv,
                            acc[2 * i + 1].x * inv, acc[2 * i + 1].y * inv);
}

// ---------------- host orchestration: dual-stream fork/join ---------------
extern "C" void kernel_launch(void* const* d_in, const int* in_sizes, int n_in,
                              void* d_out, int out_size) {
    const int*   edge_row     = (const int*)d_in[0];
    const int*   edge_col     = (const int*)d_in[1];
    const int*   batch_assign = (const int*)d_in[2];
    const float* X            = (const float*)d_in[3];
    const float* Xs           = (const float*)d_in[4];
    const float* W1           = (const float*)d_in[5];
    const float* W2           = (const float*)d_in[6];
    const float* W3           = (const float*)d_in[7];
    const float* Wl           = (const float*)d_in[8];
    const float* bl           = (const float*)d_in[9];
    float* out = (float*)d_out;

    int nE = in_sizes[0];

    float *hA, *hB, *hnv, *hsA, *hsB, *Wa, *Wb;
    __half *hhA, *hhB;
    int* rp;
    cudaGetSymbolAddress((void**)&hA,  g_hA);
    cudaGetSymbolAddress((void**)&hB,  g_hB);
    cudaGetSymbolAddress((void**)&hhA, g_hhA);
    cudaGetSymbolAddress((void**)&hhB, g_hhB);
    cudaGetSymbolAddress((void**)&hnv, g_hnv);
    cudaGetSymbolAddress((void**)&hsA, g_hsA);
    cudaGetSymbolAddress((void**)&hsB, g_hsB);
    cudaGetSymbolAddress((void**)&Wa,  g_Wa);
    cudaGetSymbolAddress((void**)&Wb,  g_Wb);
    cudaGetSymbolAddress((void**)&rp,  g_rowptr);

    cudaStream_t s1 = 0;   // capture (legacy) stream: node path
    cudaStream_t s2;       // batch path
    cudaStreamCreateWithFlags(&s2, cudaStreamNonBlocking);
    cudaEvent_t evFork, evEnd, evU[3], evP[3];
    cudaEventCreateWithFlags(&evFork, cudaEventDisableTiming);
    cudaEventCreateWithFlags(&evEnd,  cudaEventDisableTiming);
    for (int d = 0; d < 3; d++) {
        cudaEventCreateWithFlags(&evU[d], cudaEventDisableTiming);
        cudaEventCreateWithFlags(&evP[d], cudaEventDisableTiming);
    }

    int prep_blocks = 2 + INIT_BLKS + (nE + 255) / 256;
    prep<<<prep_blocks, 256, 0, s1>>>(edge_row, nE, X, Xs, W1, W2, W3, Wl,
                                      hA, hhA, hsA);
    cudaEventRecord(evFork, s1);
    cudaStreamWaitEvent(s2, evFork, 0);

    float* hc = hA;  float* hn_ = hB;
    __half* hhc = hhA; __half* hhn = hhB;
    float* hsc = hsA; float* hsn = hsB;
    for (int d = 0; d < 3; d++) {
        float* hout  = (d == 2) ? out : hn_;
        float* hsout = (d == 2) ? (out + N_NODES * D_EMB) : hsn;

        // --- node path (s1) ---
        spmm<<<(N_NODES * 32 + 255) / 256, 256, 0, s1>>>(
            (const __half2*)hhc, edge_col, rp, (float2*)hnv);

        // --- batch path (s2), independent of spmm/update_h this iter ---
        pool_partial<<<PB, 128, 0, s2>>>(hc, batch_assign, N_NODES);
        cudaEventRecord(evP[d], s2);           // WAR guard: hc stays readable
        pool_reduce<<<16, 256, 0, s2>>>();
        update_hs<<<2, 128, 0, s2>>>(hsc, bl, hsout);

        // update_h(d) writes the buffer pool_partial(d-1) was reading
        if (d > 0) cudaStreamWaitEvent(s1, evP[d - 1], 0);
        update_h<<<(N_NODES + 31) / 32, 128, 0, s1>>>(
            hc, hnv, Wa, Wb, bl, hout, hhn, N_NODES);
        cudaEventRecord(evU[d], s1);
        if (d < 2) cudaStreamWaitEvent(s2, evU[d], 0);  // next pool reads new h

        float* tf = hc; hc = hn_; hn_ = tf;
        __half* th = hhc; hhc = hhn; hhn = th;
        tf = hsc; hsc = hsn; hsn = tf;
    }

    cudaEventRecord(evEnd, s2);
    cudaStreamWaitEvent(s1, evEnd, 0);   // join: all output visible on s1
}

// round 6
// speedup vs baseline: 1.9952x; 1.3611x over previous
#include <cuda_runtime.h>
#include <cuda_fp16.h>

#define N_NODES 50000
#define NPAD    50048
#define D_EMB   64
#define N_BATCH 64
#define PB      128   // pool partial blocks
#define UH_NODES 64   // nodes per update_h block

// ---------------- scratch (device globals; no allocation) ----------------
__device__ float  g_hA[NPAD * D_EMB];
__device__ float  g_hB[NPAD * D_EMB];
__device__ __half g_hhA[NPAD * D_EMB];
__device__ __half g_hhB[NPAD * D_EMB];
__device__ float  g_hnv[NPAD * D_EMB];
__device__ float  g_hsA[N_BATCH * D_EMB];
__device__ float  g_hsB[N_BATCH * D_EMB];
__device__ float  g_Wa[D_EMB * D_EMB];
__device__ float  g_Wb[D_EMB * D_EMB];
__device__ int    g_rowptr[N_NODES + 1];
__device__ float  g_pp[PB * N_BATCH * D_EMB];
__device__ float  g_ppq[4 * N_BATCH * D_EMB];   // 4 quarter-reduced partials

// ---------------- packed f32x2 FMA (sm_103a; 2x FFMA throughput) ----------
union F2U { float2 f; unsigned long long u; };
__device__ __forceinline__ void ffma2(float2& c, float2 a, float2 b) {
    F2U A, B, C; A.f = a; B.f = b; C.f = c;
    asm("fma.rn.f32x2 %0, %1, %2, %0;" : "+l"(C.u) : "l"(A.u), "l"(B.u));
    c = C.f;
}

// ---------------- prep: fuse_w + init_h + init_hs + rowptr, one launch ----
#define INIT_BLKS ((N_NODES + 255) / 256)

__global__ void prep(const int* __restrict__ er, int nE,
                     const float* __restrict__ X, const float* __restrict__ Xs,
                     const float* __restrict__ W1, const float* __restrict__ W2,
                     const float* __restrict__ W3, const float* __restrict__ Wl,
                     float* __restrict__ h, __half* __restrict__ hh,
                     float* __restrict__ hs) {
    int b = blockIdx.x, t = threadIdx.x;
    if (b == 0) {
        for (int o = t; o < 4096; o += 256) {
            int i = o >> 6, j = o & 63;
            float sa = 0.f, sb = 0.f;
            #pragma unroll 8
            for (int k = 0; k < 64; k++) {
                sa = fmaf(W2[i * 64 + k], Wl[k * 64 + j], sa);
                sb = fmaf(W3[i * 64 + k], Wl[(64 + k) * 64 + j], sb);
            }
            g_Wa[o] = sa; g_Wb[o] = sb;
        }
    } else if (b == 1) {
        if (t < N_BATCH) {
            float x0 = Xs[t * 2], x1 = Xs[t * 2 + 1];
            float s = 0.f;
            #pragma unroll
            for (int j = 0; j < 64; j++) {
                float v = fmaxf(fmaf(x0, W1[j], x1 * W1[64 + j]), 0.f);
                s = fmaf(v, v, s);
            }
            float inv = 1.f / fmaxf(sqrtf(s), 1e-12f);
            #pragma unroll
            for (int j = 0; j < 64; j++) {
                float v = fmaxf(fmaf(x0, W1[j], x1 * W1[64 + j]), 0.f);
                hs[t * 64 + j] = v * inv;
            }
        }
    } else if (b < 2 + INIT_BLKS) {
        int n = (b - 2) * 256 + t;
        if (n < N_NODES) {
            float x0 = X[n * 2], x1 = X[n * 2 + 1];
            float s = 0.f;
            #pragma unroll
            for (int j = 0; j < 64; j++) {
                float v = fmaxf(fmaf(x0, W1[j], x1 * W1[64 + j]), 0.f);
                s = fmaf(v, v, s);
            }
            float inv = 1.f / fmaxf(sqrtf(s), 1e-12f);
            float4* h4 = (float4*)(h + n * 64);
            __half2* hh2 = (__half2*)(hh + n * 64);
            #pragma unroll
            for (int j = 0; j < 64; j += 4) {
                float v0 = fmaxf(fmaf(x0, W1[j],     x1 * W1[64 + j]),     0.f) * inv;
                float v1 = fmaxf(fmaf(x0, W1[j + 1], x1 * W1[64 + j + 1]), 0.f) * inv;
                float v2 = fmaxf(fmaf(x0, W1[j + 2], x1 * W1[64 + j + 2]), 0.f) * inv;
                float v3 = fmaxf(fmaf(x0, W1[j + 3], x1 * W1[64 + j + 3]), 0.f) * inv;
                h4[j / 4] = make_float4(v0, v1, v2, v3);
                hh2[j / 2]     = __floats2half2_rn(v0, v1);
                hh2[j / 2 + 1] = __floats2half2_rn(v2, v3);
            }
        }
    } else {
        int e = (b - (2 + INIT_BLKS)) * 256 + t;
        if (e < nE) {
            int r = er[e];
            int rprev = (e == 0) ? -1 : er[e - 1];
            for (int rr = rprev + 1; rr <= r; rr++) g_rowptr[rr] = e;
            if (e == nE - 1)
                for (int rr = r + 1; rr <= N_NODES; rr++) g_rowptr[rr] = nE;
        }
    }
}

// ---------------- SPMM (fp16 gather, 16-deep MLP) -------------------------
__global__ void spmm(const __half2* __restrict__ hh, const int* __restrict__ col,
                     const int* __restrict__ rp, float2* __restrict__ out) {
    int w = (blockIdx.x * blockDim.x + threadIdx.x) >> 5;
    if (w >= N_NODES) return;
    int lane = threadIdx.x & 31;
    int s = rp[w], e = rp[w + 1];
    float ax = 0.f, ay = 0.f, bx = 0.f, by = 0.f;
    int i = s;
    for (; i + 16 <= e; i += 16) {
        int c[16];
        #pragma unroll
        for (int u = 0; u < 16; u++) c[u] = __ldg(col + i + u);
        float2 v[16];
        #pragma unroll
        for (int u = 0; u < 16; u++) v[u] = __half22float2(hh[c[u] * 32 + lane]);
        #pragma unroll
        for (int u = 0; u < 16; u += 2) {
            ax += v[u].x;     ay += v[u].y;
            bx += v[u + 1].x; by += v[u + 1].y;
        }
    }
    for (; i + 4 <= e; i += 4) {
        int c0 = __ldg(col + i);
        int c1 = __ldg(col + i + 1);
        int c2 = __ldg(col + i + 2);
        int c3 = __ldg(col + i + 3);
        float2 v0 = __half22float2(hh[c0 * 32 + lane]);
        float2 v1 = __half22float2(hh[c1 * 32 + lane]);
        float2 v2 = __half22float2(hh[c2 * 32 + lane]);
        float2 v3 = __half22float2(hh[c3 * 32 + lane]);
        ax += v0.x + v2.x; ay += v0.y + v2.y;
        bx += v1.x + v3.x; by += v1.y + v3.y;
    }
    for (; i < e; i++) {
        float2 v = __half22float2(hh[__ldg(col + i) * 32 + lane]);
        ax += v.x; ay += v.y;
    }
    out[w * 32 + lane] = make_float2(ax + bx, ay + by);
}

// ---------------- batch pooling stage 1 (deterministic, no atomics) -------
__global__ void __launch_bounds__(128) pool_partial(const float* __restrict__ h,
                                                    const int* __restrict__ ba, int n) {
    __shared__ float acc[2 * N_BATCH * D_EMB];  // 32 KB
    int t = threadIdx.x;
    for (int i = t; i < 2 * 4096; i += 128) acc[i] = 0.f;
    __syncthreads();
    int per = (n + PB - 1) / PB;
    int start = blockIdx.x * per;
    int end = min(start + per, n);
    int j = t & 63;
    int nl = t >> 6;
    float* my = acc + nl * 4096;
    for (int nn = start + nl; nn < end; nn += 2) {
        int b = ba[nn];
        my[b * 64 + j] += h[nn * 64 + j];
    }
    __syncthreads();
    for (int i = t; i < 4096; i += 128)
        g_pp[blockIdx.x * 4096 + i] = acc[i] + acc[4096 + i];
}

// ---------------- pooling stage 2: 4096 threads, float4, 4-way K-split ----
__global__ void pool_reduce() {
    int tid = blockIdx.x * blockDim.x + threadIdx.x;  // 4096
    int q = tid >> 10, i4 = tid & 1023;
    const float4* pp = (const float4*)g_pp;
    float4 s = make_float4(0.f, 0.f, 0.f, 0.f);
    #pragma unroll 8
    for (int b = q * 32; b < q * 32 + 32; b++) {
        float4 v = pp[b * 1024 + i4];
        s.x += v.x; s.y += v.y; s.z += v.z; s.w += v.w;
    }
    ((float4*)g_ppq)[q * 1024 + i4] = s;
}

// ---------------- update_h v2: 64 nodes/block, transposed conflict-free ---
// thread t: slot=t>>2 (node pair slot, nodes slot & slot+32), part=t&3 (16 dims)
__global__ void __launch_bounds__(128) update_h(
    const float* __restrict__ h, const float* __restrict__ hnv,
    const float* __restrict__ Wa, const float* __restrict__ Wb,
    const float* __restrict__ bl, float* __restrict__ out,
    __half* __restrict__ hho, int nrows) {
    __shared__ float sWa[4096], sWb[4096];
    __shared__ float sht[4096], shnt[4096];   // transposed [k][node]
    int t = threadIdx.x;
    for (int i = t; i < 1024; i += 128) {
        ((float4*)sWa)[i] = ((const float4*)Wa)[i];
        ((float4*)sWb)[i] = ((const float4*)Wb)[i];
    }
    int base = blockIdx.x * UH_NODES;
    for (int i = t; i < 1024; i += 128) {
        int r = i >> 4, c4 = i & 15;                 // node-local, dim quad
        float4 v = ((const float4*)(h   + (base + r) * 64))[c4];
        float4 w = ((const float4*)(hnv + (base + r) * 64))[c4];
        sht [(c4 * 4 + 0) * 64 + r] = v.x;
        sht [(c4 * 4 + 1) * 64 + r] = v.y;
        sht [(c4 * 4 + 2) * 64 + r] = v.z;
        sht [(c4 * 4 + 3) * 64 + r] = v.w;
        shnt[(c4 * 4 + 0) * 64 + r] = w.x;
        shnt[(c4 * 4 + 1) * 64 + r] = w.y;
        shnt[(c4 * 4 + 2) * 64 + r] = w.z;
        shnt[(c4 * 4 + 3) * 64 + r] = w.w;
    }
    __syncthreads();

    int slot = t >> 2, part = t & 3;
    float2 acc0[8], acc1[8];
    #pragma unroll
    for (int i = 0; i < 8; i++) {
        float2 bv = ((const float2*)bl)[part * 8 + i];
        acc0[i] = bv; acc1[i] = bv;
    }

    const float4* wa4 = (const float4*)sWa;
    const float4* wb4 = (const float4*)sWb;

    #pragma unroll 4
    for (int k = 0; k < 64; k++) {
        float a0 = sht [k * 64 + slot];
        float a1 = sht [k * 64 + slot + 32];
        float b0 = shnt[k * 64 + slot];
        float b1 = shnt[k * 64 + slot + 32];
        float2 a02 = make_float2(a0, a0), a12 = make_float2(a1, a1);
        float2 b02 = make_float2(b0, b0), b12 = make_float2(b1, b1);
        #pragma unroll
        for (int i = 0; i < 4; i++) {
            float4 wa = wa4[k * 16 + part * 4 + i];
            float4 wb = wb4[k * 16 + part * 4 + i];
            float2 waxy = make_float2(wa.x, wa.y), wazw = make_float2(wa.z, wa.w);
            float2 wbxy = make_float2(wb.x, wb.y), wbzw = make_float2(wb.z, wb.w);
            ffma2(acc0[2 * i],     a02, waxy);
            ffma2(acc0[2 * i + 1], a02, wazw);
            ffma2(acc0[2 * i],     b02, wbxy);
            ffma2(acc0[2 * i + 1], b02, wbzw);
            ffma2(acc1[2 * i],     a12, waxy);
            ffma2(acc1[2 * i + 1], a12, wazw);
            ffma2(acc1[2 * i],     b12, wbxy);
            ffma2(acc1[2 * i + 1], b12, wbzw);
        }
    }

    // epilogue for both nodes: relu + l2norm across 4 parts (consecutive lanes)
    #pragma unroll
    for (int nn = 0; nn < 2; nn++) {
        float2* acc = nn ? acc1 : acc0;
        float s = 0.f;
        #pragma unroll
        for (int i = 0; i < 8; i++) {
            acc[i].x = fmaxf(acc[i].x, 0.f);
            acc[i].y = fmaxf(acc[i].y, 0.f);
            s = fmaf(acc[i].x, acc[i].x, s);
            s = fmaf(acc[i].y, acc[i].y, s);
        }
        s += __shfl_xor_sync(0xffffffffu, s, 1);
        s += __shfl_xor_sync(0xffffffffu, s, 2);
        float inv = 1.f / fmaxf(sqrtf(s), 1e-12f);

        int n = base + slot + nn * 32;
        if (n < nrows) {
            float4* o4 = (float4*)(out + n * 64 + part * 16);
            union { __half2 h2[8]; uint4 u[2]; } P;
            #pragma unroll
            for (int i = 0; i < 4; i++) {
                float x0 = acc[2 * i].x * inv, y0 = acc[2 * i].y * inv;
                float x1 = acc[2 * i + 1].x * inv, y1 = acc[2 * i + 1].y * inv;
                o4[i] = make_float4(x0, y0, x1, y1);
                P.h2[2 * i]     = __floats2half2_rn(x0, y0);
                P.h2[2 * i + 1] = __floats2half2_rn(x1, y1);
            }
            uint4* ho = (uint4*)(hho + n * 64 + part * 16);
            ho[0] = P.u[0];
            ho[1] = P.u[1];
        }
    }
}

// ---------------- batch update (folds 4-quarter reduce) -------------------
__global__ void __launch_bounds__(128) update_hs(
    const float* __restrict__ hs, const float* __restrict__ bl,
    float* __restrict__ out) {
    __shared__ float sWa[4096], sWb[4096];
    __shared__ float sh[2048], shn[2048];
    int t = threadIdx.x;
    int base = blockIdx.x * 32;
    for (int i = t; i < 1024; i += 128) {
        ((float4*)sWa)[i] = ((const float4*)g_Wa)[i];
        ((float4*)sWb)[i] = ((const float4*)g_Wb)[i];
    }
    for (int i = t; i < 512; i += 128)
        ((float4*)sh)[i] = ((const float4*)(hs + base * 64))[i];
    for (int i = t; i < 512; i += 128) {
        float4 s = make_float4(0.f, 0.f, 0.f, 0.f);
        #pragma unroll
        for (int q = 0; q < 4; q++) {
            float4 v = ((const float4*)g_ppq)[q * 1024 + base * 16 + i];
            s.x += v.x; s.y += v.y; s.z += v.z; s.w += v.w;
        }
        ((float4*)shn)[i] = s;
    }
    __syncthreads();

    int nl = t >> 2, part = t & 3;
    float2 acc[8];
    #pragma unroll
    for (int i = 0; i < 8; i++) acc[i] = ((const float2*)bl)[part * 8 + i];

    const float4* wa4 = (const float4*)sWa;
    const float4* wb4 = (const float4*)sWb;
    const float* hr = sh + nl * 64;
    const float* hnr = shn + nl * 64;

    #pragma unroll 4
    for (int k = 0; k < 64; k++) {
        float a = hr[k], b = hnr[k];
        float2 a2 = make_float2(a, a), b2 = make_float2(b, b);
        #pragma unroll
        for (int i = 0; i < 4; i++) {
            float4 wa = wa4[k * 16 + part * 4 + i];
            ffma2(acc[2 * i],     a2, make_float2(wa.x, wa.y));
            ffma2(acc[2 * i + 1], a2, make_float2(wa.z, wa.w));
            float4 wb = wb4[k * 16 + part * 4 + i];
            ffma2(acc[2 * i],     b2, make_float2(wb.x, wb.y));
            ffma2(acc[2 * i + 1], b2, make_float2(wb.z, wb.w));
        }
    }

    float s = 0.f;
    #pragma unroll
    for (int i = 0; i < 8; i++) {
        acc[i].x = fmaxf(acc[i].x, 0.f);
        acc[i].y = fmaxf(acc[i].y, 0.f);
        s = fmaf(acc[i].x, acc[i].x, s);
        s = fmaf(acc[i].y, acc[i].y, s);
    }
    s += __shfl_xor_sync(0xffffffffu, s, 1);
    s += __shfl_xor_sync(0xffffffffu, s, 2);
    float inv = 1.f / fmaxf(sqrtf(s), 1e-12f);

    float4* o4 = (float4*)(out + (base + nl) * 64 + part * 16);
    #pragma unroll
    for (int i = 0; i < 4; i++)
        o4[i] = make_float4(acc[2 * i].x * inv, acc[2 * i].y * inv,
                            acc[2 * i + 1].x * inv, acc[2 * i + 1].y * inv);
}

// ---------------- host orchestration: dual-stream fork/join ---------------
extern "C" void kernel_launch(void* const* d_in, const int* in_sizes, int n_in,
                              void* d_out, int out_size) {
    const int*   edge_row     = (const int*)d_in[0];
    const int*   edge_col     = (const int*)d_in[1];
    const int*   batch_assign = (const int*)d_in[2];
    const float* X            = (const float*)d_in[3];
    const float* Xs           = (const float*)d_in[4];
    const float* W1           = (const float*)d_in[5];
    const float* W2           = (const float*)d_in[6];
    const float* W3           = (const float*)d_in[7];
    const float* Wl           = (const float*)d_in[8];
    const float* bl           = (const float*)d_in[9];
    float* out = (float*)d_out;

    int nE = in_sizes[0];

    float *hA, *hB, *hnv, *hsA, *hsB, *Wa, *Wb;
    __half *hhA, *hhB;
    int* rp;
    cudaGetSymbolAddress((void**)&hA,  g_hA);
    cudaGetSymbolAddress((void**)&hB,  g_hB);
    cudaGetSymbolAddress((void**)&hhA, g_hhA);
    cudaGetSymbolAddress((void**)&hhB, g_hhB);
    cudaGetSymbolAddress((void**)&hnv, g_hnv);
    cudaGetSymbolAddress((void**)&hsA, g_hsA);
    cudaGetSymbolAddress((void**)&hsB, g_hsB);
    cudaGetSymbolAddress((void**)&Wa,  g_Wa);
    cudaGetSymbolAddress((void**)&Wb,  g_Wb);
    cudaGetSymbolAddress((void**)&rp,  g_rowptr);

    cudaStream_t s1 = 0;   // capture (legacy) stream: node path
    cudaStream_t s2;       // batch path
    cudaStreamCreateWithFlags(&s2, cudaStreamNonBlocking);
    cudaEvent_t evFork, evEnd, evU[3], evP[3];
    cudaEventCreateWithFlags(&evFork, cudaEventDisableTiming);
    cudaEventCreateWithFlags(&evEnd,  cudaEventDisableTiming);
    for (int d = 0; d < 3; d++) {
        cudaEventCreateWithFlags(&evU[d], cudaEventDisableTiming);
        cudaEventCreateWithFlags(&evP[d], cudaEventDisableTiming);
    }

    int prep_blocks = 2 + INIT_BLKS + (nE + 255) / 256;
    prep<<<prep_blocks, 256, 0, s1>>>(edge_row, nE, X, Xs, W1, W2, W3, Wl,
                                      hA, hhA, hsA);
    cudaEventRecord(evFork, s1);
    cudaStreamWaitEvent(s2, evFork, 0);

    float* hc = hA;  float* hn_ = hB;
    __half* hhc = hhA; __half* hhn = hhB;
    float* hsc = hsA; float* hsn = hsB;
    for (int d = 0; d < 3; d++) {
        float* hout  = (d == 2) ? out : hn_;
        float* hsout = (d == 2) ? (out + N_NODES * D_EMB) : hsn;

        if (d == 0) {
            // host-enqueue batch path first so spmm lands at ncu launch idx 5
            pool_partial<<<PB, 128, 0, s2>>>(hc, batch_assign, N_NODES);
            cudaEventRecord(evP[d], s2);
            pool_reduce<<<16, 256, 0, s2>>>();
            spmm<<<(N_NODES * 32 + 255) / 256, 256, 0, s1>>>(
                (const __half2*)hhc, edge_col, rp, (float2*)hnv);
            update_hs<<<2, 128, 0, s2>>>(hsc, bl, hsout);
        } else {
            spmm<<<(N_NODES * 32 + 255) / 256, 256, 0, s1>>>(
                (const __half2*)hhc, edge_col, rp, (float2*)hnv);
            pool_partial<<<PB, 128, 0, s2>>>(hc, batch_assign, N_NODES);
            cudaEventRecord(evP[d], s2);
            pool_reduce<<<16, 256, 0, s2>>>();
            update_hs<<<2, 128, 0, s2>>>(hsc, bl, hsout);
        }

        // update_h(d) overwrites the buffer pool_partial(d-1) read
        if (d > 0) cudaStreamWaitEvent(s1, evP[d - 1], 0);
        update_h<<<(N_NODES + UH_NODES - 1) / UH_NODES, 128, 0, s1>>>(
            hc, hnv, Wa, Wb, bl, hout, hhn, N_NODES);
        cudaEventRecord(evU[d], s1);
        if (d < 2) cudaStreamWaitEvent(s2, evU[d], 0);  // next pool reads new h

        float* tf = hc; hc = hn_; hn_ = tf;
        __half* th = hhc; hhc = hhn; hhn = th;
        tf = hsc; hsc = hsn; hsn = tf;
    }

    cudaEventRecord(evEnd, s2);
    cudaStreamWaitEvent(s1, evEnd, 0);   // join: all output visible on s1
}

// round 7
// speedup vs baseline: 2.0172x; 1.0110x over previous
#include <cuda_runtime.h>
#include <cuda_fp16.h>

#define N_NODES 50000
#define NPAD    50048
#define D_EMB   64
#define N_BATCH 64
#define PB      128   // pool partial blocks
#define UH_NODES 64   // nodes per update_h block

// ---------------- scratch (device globals; no allocation) ----------------
__device__ float  g_hA[NPAD * D_EMB];
__device__ float  g_hB[NPAD * D_EMB];
__device__ __half g_hhA[NPAD * D_EMB];
__device__ __half g_hhB[NPAD * D_EMB];
__device__ float  g_hnv[NPAD * D_EMB];
__device__ float  g_hsA[N_BATCH * D_EMB];
__device__ float  g_hsB[N_BATCH * D_EMB];
__device__ float  g_Wa[D_EMB * D_EMB];
__device__ float  g_Wb[D_EMB * D_EMB];
__device__ int    g_rowptr[N_NODES + 1];
__device__ float  g_pp[PB * N_BATCH * D_EMB];
__device__ float  g_ppq[4 * N_BATCH * D_EMB];   // 4 quarter-reduced partials

// ---------------- packed f32x2 FMA (sm_103a; 2x FFMA throughput) ----------
union F2U { float2 f; unsigned long long u; };
__device__ __forceinline__ void ffma2(float2& c, float2 a, float2 b) {
    F2U A, B, C; A.f = a; B.f = b; C.f = c;
    asm("fma.rn.f32x2 %0, %1, %2, %0;" : "+l"(C.u) : "l"(A.u), "l"(B.u));
    c = C.f;
}

// ---------------- prep: fuse_w + init_h + init_hs + rowptr, one launch ----
#define INIT_BLKS ((N_NODES + 255) / 256)

__global__ void prep(const int* __restrict__ er, int nE,
                     const float* __restrict__ X, const float* __restrict__ Xs,
                     const float* __restrict__ W1, const float* __restrict__ W2,
                     const float* __restrict__ W3, const float* __restrict__ Wl,
                     float* __restrict__ h, __half* __restrict__ hh,
                     float* __restrict__ hs) {
    __shared__ float sWl[8192];   // full Wl [128,64], 32 KB (block 0 only)
    int b = blockIdx.x, t = threadIdx.x;
    if (b == 0) {
        // stage Wl into smem (coalesced float4), then fuse: Wa=W2@Wl_top, Wb=W3@Wl_bot
        for (int i = t; i < 2048; i += 256)
            ((float4*)sWl)[i] = ((const float4*)Wl)[i];
        __syncthreads();
        for (int o = t; o < 4096; o += 256) {
            int i = o >> 6, j = o & 63;
            float sa = 0.f, sb = 0.f;
            #pragma unroll 8
            for (int k = 0; k < 64; k++) {
                sa = fmaf(W2[i * 64 + k], sWl[k * 64 + j], sa);
                sb = fmaf(W3[i * 64 + k], sWl[(64 + k) * 64 + j], sb);
            }
            g_Wa[o] = sa; g_Wb[o] = sb;
        }
    } else if (b == 1) {
        if (t < N_BATCH) {
            float x0 = Xs[t * 2], x1 = Xs[t * 2 + 1];
            float s = 0.f;
            #pragma unroll
            for (int j = 0; j < 64; j++) {
                float v = fmaxf(fmaf(x0, W1[j], x1 * W1[64 + j]), 0.f);
                s = fmaf(v, v, s);
            }
            float inv = 1.f / fmaxf(sqrtf(s), 1e-12f);
            #pragma unroll
            for (int j = 0; j < 64; j++) {
                float v = fmaxf(fmaf(x0, W1[j], x1 * W1[64 + j]), 0.f);
                hs[t * 64 + j] = v * inv;
            }
        }
    } else if (b < 2 + INIT_BLKS) {
        int n = (b - 2) * 256 + t;
        if (n < N_NODES) {
            float x0 = X[n * 2], x1 = X[n * 2 + 1];
            float s = 0.f;
            #pragma unroll
            for (int j = 0; j < 64; j++) {
                float v = fmaxf(fmaf(x0, W1[j], x1 * W1[64 + j]), 0.f);
                s = fmaf(v, v, s);
            }
            float inv = 1.f / fmaxf(sqrtf(s), 1e-12f);
            float4* h4 = (float4*)(h + n * 64);
            __half2* hh2 = (__half2*)(hh + n * 64);
            #pragma unroll
            for (int j = 0; j < 64; j += 4) {
                float v0 = fmaxf(fmaf(x0, W1[j],     x1 * W1[64 + j]),     0.f) * inv;
                float v1 = fmaxf(fmaf(x0, W1[j + 1], x1 * W1[64 + j + 1]), 0.f) * inv;
                float v2 = fmaxf(fmaf(x0, W1[j + 2], x1 * W1[64 + j + 2]), 0.f) * inv;
                float v3 = fmaxf(fmaf(x0, W1[j + 3], x1 * W1[64 + j + 3]), 0.f) * inv;
                h4[j / 4] = make_float4(v0, v1, v2, v3);
                hh2[j / 2]     = __floats2half2_rn(v0, v1);
                hh2[j / 2 + 1] = __floats2half2_rn(v2, v3);
            }
        }
    } else {
        int e = (b - (2 + INIT_BLKS)) * 256 + t;
        if (e < nE) {
            int r = er[e];
            int rprev = (e == 0) ? -1 : er[e - 1];
            for (int rr = rprev + 1; rr <= r; rr++) g_rowptr[rr] = e;
            if (e == nE - 1)
                for (int rr = r + 1; rr <= N_NODES; rr++) g_rowptr[rr] = nE;
        }
    }
}

// ---------------- SPMM (fp16 gather, 16-deep MLP) -------------------------
__global__ void spmm(const __half2* __restrict__ hh, const int* __restrict__ col,
                     const int* __restrict__ rp, float2* __restrict__ out) {
    int w = (blockIdx.x * blockDim.x + threadIdx.x) >> 5;
    if (w >= N_NODES) return;
    int lane = threadIdx.x & 31;
    int s = rp[w], e = rp[w + 1];
    float ax = 0.f, ay = 0.f, bx = 0.f, by = 0.f;
    int i = s;
    for (; i + 16 <= e; i += 16) {
        int c[16];
        #pragma unroll
        for (int u = 0; u < 16; u++) c[u] = __ldg(col + i + u);
        float2 v[16];
        #pragma unroll
        for (int u = 0; u < 16; u++) v[u] = __half22float2(hh[c[u] * 32 + lane]);
        #pragma unroll
        for (int u = 0; u < 16; u += 2) {
            ax += v[u].x;     ay += v[u].y;
            bx += v[u + 1].x; by += v[u + 1].y;
        }
    }
    for (; i + 4 <= e; i += 4) {
        int c0 = __ldg(col + i);
        int c1 = __ldg(col + i + 1);
        int c2 = __ldg(col + i + 2);
        int c3 = __ldg(col + i + 3);
        float2 v0 = __half22float2(hh[c0 * 32 + lane]);
        float2 v1 = __half22float2(hh[c1 * 32 + lane]);
        float2 v2 = __half22float2(hh[c2 * 32 + lane]);
        float2 v3 = __half22float2(hh[c3 * 32 + lane]);
        ax += v0.x + v2.x; ay += v0.y + v2.y;
        bx += v1.x + v3.x; by += v1.y + v3.y;
    }
    for (; i < e; i++) {
        float2 v = __half22float2(hh[__ldg(col + i) * 32 + lane]);
        ax += v.x; ay += v.y;
    }
    out[w * 32 + lane] = make_float2(ax + bx, ay + by);
}

// ---------------- batch pooling stage 1 (deterministic, no atomics) -------
__global__ void __launch_bounds__(128) pool_partial(const float* __restrict__ h,
                                                    const int* __restrict__ ba, int n) {
    __shared__ float acc[2 * N_BATCH * D_EMB];  // 32 KB
    int t = threadIdx.x;
    for (int i = t; i < 2 * 4096; i += 128) acc[i] = 0.f;
    __syncthreads();
    int per = (n + PB - 1) / PB;
    int start = blockIdx.x * per;
    int end = min(start + per, n);
    int j = t & 63;
    int nl = t >> 6;
    float* my = acc + nl * 4096;
    for (int nn = start + nl; nn < end; nn += 2) {
        int b = ba[nn];
        my[b * 64 + j] += h[nn * 64 + j];
    }
    __syncthreads();
    for (int i = t; i < 4096; i += 128)
        g_pp[blockIdx.x * 4096 + i] = acc[i] + acc[4096 + i];
}

// ---------------- pooling stage 2: 4096 threads, float4, 4-way K-split ----
__global__ void pool_reduce() {
    int tid = blockIdx.x * blockDim.x + threadIdx.x;  // 4096
    int q = tid >> 10, i4 = tid & 1023;
    const float4* pp = (const float4*)g_pp;
    float4 s = make_float4(0.f, 0.f, 0.f, 0.f);
    #pragma unroll 8
    for (int b = q * 32; b < q * 32 + 32; b++) {
        float4 v = pp[b * 1024 + i4];
        s.x += v.x; s.y += v.y; s.z += v.z; s.w += v.w;
    }
    ((float4*)g_ppq)[q * 1024 + i4] = s;
}

// ---------------- update_h v2: 64 nodes/block, transposed conflict-free ---
__global__ void __launch_bounds__(128, 3) update_h(
    const float* __restrict__ h, const float* __restrict__ hnv,
    const float* __restrict__ Wa, const float* __restrict__ Wb,
    const float* __restrict__ bl, float* __restrict__ out,
    __half* __restrict__ hho, int nrows) {
    __shared__ float sWa[4096], sWb[4096];
    __shared__ float sht[4096], shnt[4096];   // transposed [k][node]
    int t = threadIdx.x;
    for (int i = t; i < 1024; i += 128) {
        ((float4*)sWa)[i] = ((const float4*)Wa)[i];
        ((float4*)sWb)[i] = ((const float4*)Wb)[i];
    }
    int base = blockIdx.x * UH_NODES;
    for (int i = t; i < 1024; i += 128) {
        int r = i >> 4, c4 = i & 15;                 // node-local, dim quad
        float4 v = ((const float4*)(h   + (base + r) * 64))[c4];
        float4 w = ((const float4*)(hnv + (base + r) * 64))[c4];
        sht [(c4 * 4 + 0) * 64 + r] = v.x;
        sht [(c4 * 4 + 1) * 64 + r] = v.y;
        sht [(c4 * 4 + 2) * 64 + r] = v.z;
        sht [(c4 * 4 + 3) * 64 + r] = v.w;
        shnt[(c4 * 4 + 0) * 64 + r] = w.x;
        shnt[(c4 * 4 + 1) * 64 + r] = w.y;
        shnt[(c4 * 4 + 2) * 64 + r] = w.z;
        shnt[(c4 * 4 + 3) * 64 + r] = w.w;
    }
    __syncthreads();

    int slot = t >> 2, part = t & 3;
    float2 acc0[8], acc1[8];
    #pragma unroll
    for (int i = 0; i < 8; i++) {
        float2 bv = ((const float2*)bl)[part * 8 + i];
        acc0[i] = bv; acc1[i] = bv;
    }

    const float4* wa4 = (const float4*)sWa;
    const float4* wb4 = (const float4*)sWb;

    #pragma unroll 4
    for (int k = 0; k < 64; k++) {
        float a0 = sht [k * 64 + slot];
        float a1 = sht [k * 64 + slot + 32];
        float b0 = shnt[k * 64 + slot];
        float b1 = shnt[k * 64 + slot + 32];
        float2 a02 = make_float2(a0, a0), a12 = make_float2(a1, a1);
        float2 b02 = make_float2(b0, b0), b12 = make_float2(b1, b1);
        #pragma unroll
        for (int i = 0; i < 4; i++) {
            float4 wa = wa4[k * 16 + part * 4 + i];
            float4 wb = wb4[k * 16 + part * 4 + i];
            float2 waxy = make_float2(wa.x, wa.y), wazw = make_float2(wa.z, wa.w);
            float2 wbxy = make_float2(wb.x, wb.y), wbzw = make_float2(wb.z, wb.w);
            ffma2(acc0[2 * i],     a02, waxy);
            ffma2(acc0[2 * i + 1], a02, wazw);
            ffma2(acc0[2 * i],     b02, wbxy);
            ffma2(acc0[2 * i + 1], b02, wbzw);
            ffma2(acc1[2 * i],     a12, waxy);
            ffma2(acc1[2 * i + 1], a12, wazw);
            ffma2(acc1[2 * i],     b12, wbxy);
            ffma2(acc1[2 * i + 1], b12, wbzw);
        }
    }

    #pragma unroll
    for (int nn = 0; nn < 2; nn++) {
        float2* acc = nn ? acc1 : acc0;
        float s = 0.f;
        #pragma unroll
        for (int i = 0; i < 8; i++) {
            acc[i].x = fmaxf(acc[i].x, 0.f);
            acc[i].y = fmaxf(acc[i].y, 0.f);
            s = fmaf(acc[i].x, acc[i].x, s);
            s = fmaf(acc[i].y, acc[i].y, s);
        }
        s += __shfl_xor_sync(0xffffffffu, s, 1);
        s += __shfl_xor_sync(0xffffffffu, s, 2);
        float inv = 1.f / fmaxf(sqrtf(s), 1e-12f);

        int n = base + slot + nn * 32;
        if (n < nrows) {
            float4* o4 = (float4*)(out + n * 64 + part * 16);
            union { __half2 h2[8]; uint4 u[2]; } P;
            #pragma unroll
            for (int i = 0; i < 4; i++) {
                float x0 = acc[2 * i].x * inv, y0 = acc[2 * i].y * inv;
                float x1 = acc[2 * i + 1].x * inv, y1 = acc[2 * i + 1].y * inv;
                o4[i] = make_float4(x0, y0, x1, y1);
                P.h2[2 * i]     = __floats2half2_rn(x0, y0);
                P.h2[2 * i + 1] = __floats2half2_rn(x1, y1);
            }
            uint4* ho = (uint4*)(hho + n * 64 + part * 16);
            ho[0] = P.u[0];
            ho[1] = P.u[1];
        }
    }
}

// ---------------- batch update (folds 4-quarter reduce) -------------------
__global__ void __launch_bounds__(128) update_hs(
    const float* __restrict__ hs, const float* __restrict__ bl,
    float* __restrict__ out) {
    __shared__ float sWa[4096], sWb[4096];
    __shared__ float sh[2048], shn[2048];
    int t = threadIdx.x;
    int base = blockIdx.x * 32;
    for (int i = t; i < 1024; i += 128) {
        ((float4*)sWa)[i] = ((const float4*)g_Wa)[i];
        ((float4*)sWb)[i] = ((const float4*)g_Wb)[i];
    }
    for (int i = t; i < 512; i += 128)
        ((float4*)sh)[i] = ((const float4*)(hs + base * 64))[i];
    for (int i = t; i < 512; i += 128) {
        float4 s = make_float4(0.f, 0.f, 0.f, 0.f);
        #pragma unroll
        for (int q = 0; q < 4; q++) {
            float4 v = ((const float4*)g_ppq)[q * 1024 + base * 16 + i];
            s.x += v.x; s.y += v.y; s.z += v.z; s.w += v.w;
        }
        ((float4*)shn)[i] = s;
    }
    __syncthreads();

    int nl = t >> 2, part = t & 3;
    float2 acc[8];
    #pragma unroll
    for (int i = 0; i < 8; i++) acc[i] = ((const float2*)bl)[part * 8 + i];

    const float4* wa4 = (const float4*)sWa;
    const float4* wb4 = (const float4*)sWb;
    const float* hr = sh + nl * 64;
    const float* hnr = shn + nl * 64;

    #pragma unroll 4
    for (int k = 0; k < 64; k++) {
        float a = hr[k], b = hnr[k];
        float2 a2 = make_float2(a, a), b2 = make_float2(b, b);
        #pragma unroll
        for (int i = 0; i < 4; i++) {
            float4 wa = wa4[k * 16 + part * 4 + i];
            ffma2(acc[2 * i],     a2, make_float2(wa.x, wa.y));
            ffma2(acc[2 * i + 1], a2, make_float2(wa.z, wa.w));
            float4 wb = wb4[k * 16 + part * 4 + i];
            ffma2(acc[2 * i],     b2, make_float2(wb.x, wb.y));
            ffma2(acc[2 * i + 1], b2, make_float2(wb.z, wb.w));
        }
    }

    float s = 0.f;
    #pragma unroll
    for (int i = 0; i < 8; i++) {
        acc[i].x = fmaxf(acc[i].x, 0.f);
        acc[i].y = fmaxf(acc[i].y, 0.f);
        s = fmaf(acc[i].x, acc[i].x, s);
        s = fmaf(acc[i].y, acc[i].y, s);
    }
    s += __shfl_xor_sync(0xffffffffu, s, 1);
    s += __shfl_xor_sync(0xffffffffu, s, 2);
    float inv = 1.f / fmaxf(sqrtf(s), 1e-12f);

    float4* o4 = (float4*)(out + (base + nl) * 64 + part * 16);
    #pragma unroll
    for (int i = 0; i < 4; i++)
        o4[i] = make_float4(acc[2 * i].x * inv, acc[2 * i].y * inv,
                            acc[2 * i + 1].x * inv, acc[2 * i + 1].y * inv);
}

// ---------------- host orchestration: dual-stream fork/join ---------------
extern "C" void kernel_launch(void* const* d_in, const int* in_sizes, int n_in,
                              void* d_out, int out_size) {
    const int*   edge_row     = (const int*)d_in[0];
    const int*   edge_col     = (const int*)d_in[1];
    const int*   batch_assign = (const int*)d_in[2];
    const float* X            = (const float*)d_in[3];
    const float* Xs           = (const float*)d_in[4];
    const float* W1           = (const float*)d_in[5];
    const float* W2           = (const float*)d_in[6];
    const float* W3           = (const float*)d_in[7];
    const float* Wl           = (const float*)d_in[8];
    const float* bl           = (const float*)d_in[9];
    float* out = (float*)d_out;

    int nE = in_sizes[0];

    float *hA, *hB, *hnv, *hsA, *hsB, *Wa, *Wb;
    __half *hhA, *hhB;
    int* rp;
    cudaGetSymbolAddress((void**)&hA,  g_hA);
    cudaGetSymbolAddress((void**)&hB,  g_hB);
    cudaGetSymbolAddress((void**)&hhA, g_hhA);
    cudaGetSymbolAddress((void**)&hhB, g_hhB);
    cudaGetSymbolAddress((void**)&hnv, g_hnv);
    cudaGetSymbolAddress((void**)&hsA, g_hsA);
    cudaGetSymbolAddress((void**)&hsB, g_hsB);
    cudaGetSymbolAddress((void**)&Wa,  g_Wa);
    cudaGetSymbolAddress((void**)&Wb,  g_Wb);
    cudaGetSymbolAddress((void**)&rp,  g_rowptr);

    cudaStream_t s1 = 0;   // capture (legacy) stream: node path
    cudaStream_t s2;       // batch path
    cudaStreamCreateWithFlags(&s2, cudaStreamNonBlocking);
    cudaEvent_t evFork, evEnd, evU[3], evP[3];
    cudaEventCreateWithFlags(&evFork, cudaEventDisableTiming);
    cudaEventCreateWithFlags(&evEnd,  cudaEventDisableTiming);
    for (int d = 0; d < 3; d++) {
        cudaEventCreateWithFlags(&evU[d], cudaEventDisableTiming);
        cudaEventCreateWithFlags(&evP[d], cudaEventDisableTiming);
    }

    int prep_blocks = 2 + INIT_BLKS + (nE + 255) / 256;
    prep<<<prep_blocks, 256, 0, s1>>>(edge_row, nE, X, Xs, W1, W2, W3, Wl,
                                      hA, hhA, hsA);
    cudaEventRecord(evFork, s1);
    cudaStreamWaitEvent(s2, evFork, 0);

    float* hc = hA;  float* hn_ = hB;
    __half* hhc = hhA; __half* hhn = hhB;
    float* hsc = hsA; float* hsn = hsB;
    for (int d = 0; d < 3; d++) {
        float* hout  = (d == 2) ? out : hn_;
        float* hsout = (d == 2) ? (out + N_NODES * D_EMB) : hsn;

        if (d == 0) {
            // host order: prep[2], spmm[3], pool_partial[4], update_h[5] -> ncu -s5
            spmm<<<(N_NODES * 32 + 255) / 256, 256, 0, s1>>>(
                (const __half2*)hhc, edge_col, rp, (float2*)hnv);
            pool_partial<<<PB, 128, 0, s2>>>(hc, batch_assign, N_NODES);
            cudaEventRecord(evP[d], s2);
            update_h<<<(N_NODES + UH_NODES - 1) / UH_NODES, 128, 0, s1>>>(
                hc, hnv, Wa, Wb, bl, hout, hhn, N_NODES);
            cudaEventRecord(evU[d], s1);
            pool_reduce<<<16, 256, 0, s2>>>();
            update_hs<<<2, 128, 0, s2>>>(hsc, bl, hsout);
            cudaStreamWaitEvent(s2, evU[d], 0);  // next pool reads new h
        } else {
            spmm<<<(N_NODES * 32 + 255) / 256, 256, 0, s1>>>(
                (const __half2*)hhc, edge_col, rp, (float2*)hnv);
            pool_partial<<<PB, 128, 0, s2>>>(hc, batch_assign, N_NODES);
            cudaEventRecord(evP[d], s2);
            pool_reduce<<<16, 256, 0, s2>>>();
            update_hs<<<2, 128, 0, s2>>>(hsc, bl, hsout);

            cudaStreamWaitEvent(s1, evP[d - 1], 0);
            update_h<<<(N_NODES + UH_NODES - 1) / UH_NODES, 128, 0, s1>>>(
                hc, hnv, Wa, Wb, bl, hout, hhn, N_NODES);
            cudaEventRecord(evU[d], s1);
            if (d < 2) cudaStreamWaitEvent(s2, evU[d], 0);
        }

        float* tf = hc; hc = hn_; hn_ = tf;
        __half* th = hhc; hhc = hhn; hhn = th;
        tf = hsc; hsc = hsn; hsn = tf;
    }

    cudaEventRecord(evEnd, s2);
    cudaStreamWaitEvent(s1, evEnd, 0);   // join: all output visible on s1
}

// round 8
// speedup vs baseline: 2.2357x; 1.1083x over previous
#include <cuda_runtime.h>
#include <cuda_fp16.h>

#define N_NODES 50000
#define NPAD    50048
#define D_EMB   64
#define N_BATCH 64
#define PB      128   // pool partial blocks
#define UH_NODES 64   // nodes per update_h block
#define TSTRIDE 72    // padded fp16 tile row stride (halves)

// ---------------- scratch (device globals; no allocation) ----------------
__device__ float  g_hA[NPAD * D_EMB];
__device__ float  g_hB[NPAD * D_EMB];
__device__ __half g_hhA[NPAD * D_EMB];
__device__ __half g_hhB[NPAD * D_EMB];
__device__ __half g_hnv[NPAD * D_EMB];          // fp16 spmm output
__device__ float  g_hsA[N_BATCH * D_EMB];
__device__ float  g_hsB[N_BATCH * D_EMB];
__device__ float  g_Wa[D_EMB * D_EMB];
__device__ float  g_Wb[D_EMB * D_EMB];
__device__ __half g_Wah[D_EMB * D_EMB];         // fp16 weight copies
__device__ __half g_Wbh[D_EMB * D_EMB];
__device__ int    g_rowptr[N_NODES + 1];
__device__ float  g_pp[PB * N_BATCH * D_EMB];
__device__ float  g_ppq[4 * N_BATCH * D_EMB];

// ---------------- packed f32x2 FMA (sm_103a; 2x FFMA throughput) ----------
union F2U { float2 f; unsigned long long u; };
__device__ __forceinline__ void ffma2(float2& c, float2 a, float2 b) {
    F2U A, B, C; A.f = a; B.f = b; C.f = c;
    asm("fma.rn.f32x2 %0, %1, %2, %0;" : "+l"(C.u) : "l"(A.u), "l"(B.u));
    c = C.f;
}

// ---------------- prep: fuse_w + init_h + init_hs + rowptr, one launch ----
#define INIT_BLKS ((N_NODES + 255) / 256)

__global__ void prep(const int* __restrict__ er, int nE,
                     const float* __restrict__ X, const float* __restrict__ Xs,
                     const float* __restrict__ W1, const float* __restrict__ W2,
                     const float* __restrict__ W3, const float* __restrict__ Wl,
                     float* __restrict__ h, __half* __restrict__ hh,
                     float* __restrict__ hs) {
    __shared__ float sWl[8192];   // full Wl [128,64], 32 KB (block 0 only)
    int b = blockIdx.x, t = threadIdx.x;
    if (b == 0) {
        for (int i = t; i < 2048; i += 256)
            ((float4*)sWl)[i] = ((const float4*)Wl)[i];
        __syncthreads();
        for (int o = t; o < 4096; o += 256) {
            int i = o >> 6, j = o & 63;
            float sa = 0.f, sb = 0.f;
            #pragma unroll 8
            for (int k = 0; k < 64; k++) {
                sa = fmaf(W2[i * 64 + k], sWl[k * 64 + j], sa);
                sb = fmaf(W3[i * 64 + k], sWl[(64 + k) * 64 + j], sb);
            }
            g_Wa[o] = sa; g_Wb[o] = sb;
            g_Wah[o] = __float2half(sa);
            g_Wbh[o] = __float2half(sb);
        }
    } else if (b == 1) {
        if (t < N_BATCH) {
            float x0 = Xs[t * 2], x1 = Xs[t * 2 + 1];
            float s = 0.f;
            #pragma unroll
            for (int j = 0; j < 64; j++) {
                float v = fmaxf(fmaf(x0, W1[j], x1 * W1[64 + j]), 0.f);
                s = fmaf(v, v, s);
            }
            float inv = 1.f / fmaxf(sqrtf(s), 1e-12f);
            #pragma unroll
            for (int j = 0; j < 64; j++) {
                float v = fmaxf(fmaf(x0, W1[j], x1 * W1[64 + j]), 0.f);
                hs[t * 64 + j] = v * inv;
            }
        }
    } else if (b < 2 + INIT_BLKS) {
        int n = (b - 2) * 256 + t;
        if (n < N_NODES) {
            float x0 = X[n * 2], x1 = X[n * 2 + 1];
            float s = 0.f;
            #pragma unroll
            for (int j = 0; j < 64; j++) {
                float v = fmaxf(fmaf(x0, W1[j], x1 * W1[64 + j]), 0.f);
                s = fmaf(v, v, s);
            }
            float inv = 1.f / fmaxf(sqrtf(s), 1e-12f);
            float4* h4 = (float4*)(h + n * 64);
            __half2* hh2 = (__half2*)(hh + n * 64);
            #pragma unroll
            for (int j = 0; j < 64; j += 4) {
                float v0 = fmaxf(fmaf(x0, W1[j],     x1 * W1[64 + j]),     0.f) * inv;
                float v1 = fmaxf(fmaf(x0, W1[j + 1], x1 * W1[64 + j + 1]), 0.f) * inv;
                float v2 = fmaxf(fmaf(x0, W1[j + 2], x1 * W1[64 + j + 2]), 0.f) * inv;
                float v3 = fmaxf(fmaf(x0, W1[j + 3], x1 * W1[64 + j + 3]), 0.f) * inv;
                h4[j / 4] = make_float4(v0, v1, v2, v3);
                hh2[j / 2]     = __floats2half2_rn(v0, v1);
                hh2[j / 2 + 1] = __floats2half2_rn(v2, v3);
            }
        }
    } else {
        int e = (b - (2 + INIT_BLKS)) * 256 + t;
        if (e < nE) {
            int r = er[e];
            int rprev = (e == 0) ? -1 : er[e - 1];
            for (int rr = rprev + 1; rr <= r; rr++) g_rowptr[rr] = e;
            if (e == nE - 1)
                for (int rr = r + 1; rr <= N_NODES; rr++) g_rowptr[rr] = nE;
        }
    }
}

// ---------------- SPMM (fp16 gather, 16-deep MLP; fp16 output) ------------
__global__ void spmm(const __half2* __restrict__ hh, const int* __restrict__ col,
                     const int* __restrict__ rp, __half2* __restrict__ out) {
    int w = (blockIdx.x * blockDim.x + threadIdx.x) >> 5;
    if (w >= N_NODES) return;
    int lane = threadIdx.x & 31;
    int s = rp[w], e = rp[w + 1];
    float ax = 0.f, ay = 0.f, bx = 0.f, by = 0.f;
    int i = s;
    for (; i + 16 <= e; i += 16) {
        int c[16];
        #pragma unroll
        for (int u = 0; u < 16; u++) c[u] = __ldg(col + i + u);
        float2 v[16];
        #pragma unroll
        for (int u = 0; u < 16; u++) v[u] = __half22float2(hh[c[u] * 32 + lane]);
        #pragma unroll
        for (int u = 0; u < 16; u += 2) {
            ax += v[u].x;     ay += v[u].y;
            bx += v[u + 1].x; by += v[u + 1].y;
        }
    }
    for (; i + 4 <= e; i += 4) {
        int c0 = __ldg(col + i);
        int c1 = __ldg(col + i + 1);
        int c2 = __ldg(col + i + 2);
        int c3 = __ldg(col + i + 3);
        float2 v0 = __half22float2(hh[c0 * 32 + lane]);
        float2 v1 = __half22float2(hh[c1 * 32 + lane]);
        float2 v2 = __half22float2(hh[c2 * 32 + lane]);
        float2 v3 = __half22float2(hh[c3 * 32 + lane]);
        ax += v0.x + v2.x; ay += v0.y + v2.y;
        bx += v1.x + v3.x; by += v1.y + v3.y;
    }
    for (; i < e; i++) {
        float2 v = __half22float2(hh[__ldg(col + i) * 32 + lane]);
        ax += v.x; ay += v.y;
    }
    out[w * 32 + lane] = __floats2half2_rn(ax + bx, ay + by);
}

// ---------------- batch pooling stage 1 (deterministic, no atomics) -------
__global__ void __launch_bounds__(128) pool_partial(const float* __restrict__ h,
                                                    const int* __restrict__ ba, int n) {
    __shared__ float acc[2 * N_BATCH * D_EMB];  // 32 KB
    int t = threadIdx.x;
    for (int i = t; i < 2 * 4096; i += 128) acc[i] = 0.f;
    __syncthreads();
    int per = (n + PB - 1) / PB;
    int start = blockIdx.x * per;
    int end = min(start + per, n);
    int j = t & 63;
    int nl = t >> 6;
    float* my = acc + nl * 4096;
    for (int nn = start + nl; nn < end; nn += 2) {
        int b = ba[nn];
        my[b * 64 + j] += h[nn * 64 + j];
    }
    __syncthreads();
    for (int i = t; i < 4096; i += 128)
        g_pp[blockIdx.x * 4096 + i] = acc[i] + acc[4096 + i];
}

// ---------------- pooling stage 2: 4096 threads, float4, 4-way K-split ----
__global__ void pool_reduce() {
    int tid = blockIdx.x * blockDim.x + threadIdx.x;  // 4096
    int q = tid >> 10, i4 = tid & 1023;
    const float4* pp = (const float4*)g_pp;
    float4 s = make_float4(0.f, 0.f, 0.f, 0.f);
    #pragma unroll 8
    for (int b = q * 32; b < q * 32 + 32; b++) {
        float4 v = pp[b * 1024 + i4];
        s.x += v.x; s.y += v.y; s.z += v.z; s.w += v.w;
    }
    ((float4*)g_ppq)[q * 1024 + i4] = s;
}

// ---------------- update_h v3: fp16 tiles (padded), fp32 smem weights -----
// smem 50KB -> 4 blocks/SM. thread: slot=t>>2 (nodes slot,slot+32), part=t&3
__global__ void __launch_bounds__(128, 4) update_h(
    const __half* __restrict__ hhin, const __half* __restrict__ hnv,
    const __half* __restrict__ Wah, const __half* __restrict__ Wbh,
    const float* __restrict__ bl, float* __restrict__ out,
    __half* __restrict__ hho, int nrows) {
    __shared__ float  sWa[4096], sWb[4096];            // 32 KB fp32
    __shared__ __half sht[64 * TSTRIDE], shnt[64 * TSTRIDE];  // 18 KB fp16
    int t = threadIdx.x;
    // expand fp16 weights -> fp32 smem (one time)
    for (int i = t; i < 512; i += 128) {
        uint4 va = ((const uint4*)Wah)[i];
        uint4 vb = ((const uint4*)Wbh)[i];
        const __half2* ha = (const __half2*)&va;
        const __half2* hb = (const __half2*)&vb;
        #pragma unroll
        for (int j = 0; j < 4; j++) {
            float2 fa = __half22float2(ha[j]);
            float2 fb = __half22float2(hb[j]);
            sWa[i * 8 + 2 * j]     = fa.x;
            sWa[i * 8 + 2 * j + 1] = fa.y;
            sWb[i * 8 + 2 * j]     = fb.x;
            sWb[i * 8 + 2 * j + 1] = fb.y;
        }
    }
    int base = blockIdx.x * UH_NODES;
    for (int i = t; i < 512; i += 128) {
        int r = i >> 3, c = i & 7;
        uint4 v = ((const uint4*)(hhin + (size_t)(base + r) * 64))[c];
        uint4 w = ((const uint4*)(hnv  + (size_t)(base + r) * 64))[c];
        *(uint4*)(sht  + r * TSTRIDE + c * 8) = v;
        *(uint4*)(shnt + r * TSTRIDE + c * 8) = w;
    }
    __syncthreads();

    int slot = t >> 2, part = t & 3;
    float2 acc0[8], acc1[8];
    #pragma unroll
    for (int i = 0; i < 8; i++) {
        float2 bv = ((const float2*)bl)[part * 8 + i];
        acc0[i] = bv; acc1[i] = bv;
    }

    const float4* wa4 = (const float4*)sWa;
    const float4* wb4 = (const float4*)sWb;
    const __half* h0 = sht + slot * TSTRIDE;
    const __half* h1 = sht + (slot + 32) * TSTRIDE;
    const __half* n0 = shnt + slot * TSTRIDE;
    const __half* n1 = shnt + (slot + 32) * TSTRIDE;

    #pragma unroll 4
    for (int k = 0; k < 64; k++) {
        float a0 = __half2float(h0[k]);
        float a1 = __half2float(h1[k]);
        float b0 = __half2float(n0[k]);
        float b1 = __half2float(n1[k]);
        float2 a02 = make_float2(a0, a0), a12 = make_float2(a1, a1);
        float2 b02 = make_float2(b0, b0), b12 = make_float2(b1, b1);
        #pragma unroll
        for (int i = 0; i < 4; i++) {
            float4 wa = wa4[k * 16 + part * 4 + i];
            float4 wb = wb4[k * 16 + part * 4 + i];
            float2 waxy = make_float2(wa.x, wa.y), wazw = make_float2(wa.z, wa.w);
            float2 wbxy = make_float2(wb.x, wb.y), wbzw = make_float2(wb.z, wb.w);
            ffma2(acc0[2 * i],     a02, waxy);
            ffma2(acc0[2 * i + 1], a02, wazw);
            ffma2(acc0[2 * i],     b02, wbxy);
            ffma2(acc0[2 * i + 1], b02, wbzw);
            ffma2(acc1[2 * i],     a12, waxy);
            ffma2(acc1[2 * i + 1], a12, wazw);
            ffma2(acc1[2 * i],     b12, wbxy);
            ffma2(acc1[2 * i + 1], b12, wbzw);
        }
    }

    #pragma unroll
    for (int nn = 0; nn < 2; nn++) {
        float2* acc = nn ? acc1 : acc0;
        float s = 0.f;
        #pragma unroll
        for (int i = 0; i < 8; i++) {
            acc[i].x = fmaxf(acc[i].x, 0.f);
            acc[i].y = fmaxf(acc[i].y, 0.f);
            s = fmaf(acc[i].x, acc[i].x, s);
            s = fmaf(acc[i].y, acc[i].y, s);
        }
        s += __shfl_xor_sync(0xffffffffu, s, 1);
        s += __shfl_xor_sync(0xffffffffu, s, 2);
        float inv = 1.f / fmaxf(sqrtf(s), 1e-12f);

        int n = base + slot + nn * 32;
        if (n < nrows) {
            float4* o4 = (float4*)(out + n * 64 + part * 16);
            union { __half2 h2[8]; uint4 u[2]; } P;
            #pragma unroll
            for (int i = 0; i < 4; i++) {
                float x0 = acc[2 * i].x * inv, y0 = acc[2 * i].y * inv;
                float x1 = acc[2 * i + 1].x * inv, y1 = acc[2 * i + 1].y * inv;
                o4[i] = make_float4(x0, y0, x1, y1);
                P.h2[2 * i]     = __floats2half2_rn(x0, y0);
                P.h2[2 * i + 1] = __floats2half2_rn(x1, y1);
            }
            uint4* ho = (uint4*)(hho + n * 64 + part * 16);
            ho[0] = P.u[0];
            ho[1] = P.u[1];
        }
    }
}

// ---------------- batch update (folds 4-quarter reduce) -------------------
__global__ void __launch_bounds__(128) update_hs(
    const float* __restrict__ hs, const float* __restrict__ bl,
    float* __restrict__ out) {
    __shared__ float sWa[4096], sWb[4096];
    __shared__ float sh[2048], shn[2048];
    int t = threadIdx.x;
    int base = blockIdx.x * 32;
    for (int i = t; i < 1024; i += 128) {
        ((float4*)sWa)[i] = ((const float4*)g_Wa)[i];
        ((float4*)sWb)[i] = ((const float4*)g_Wb)[i];
    }
    for (int i = t; i < 512; i += 128)
        ((float4*)sh)[i] = ((const float4*)(hs + base * 64))[i];
    for (int i = t; i < 512; i += 128) {
        float4 s = make_float4(0.f, 0.f, 0.f, 0.f);
        #pragma unroll
        for (int q = 0; q < 4; q++) {
            float4 v = ((const float4*)g_ppq)[q * 1024 + base * 16 + i];
            s.x += v.x; s.y += v.y; s.z += v.z; s.w += v.w;
        }
        ((float4*)shn)[i] = s;
    }
    __syncthreads();

    int nl = t >> 2, part = t & 3;
    float2 acc[8];
    #pragma unroll
    for (int i = 0; i < 8; i++) acc[i] = ((const float2*)bl)[part * 8 + i];

    const float4* wa4 = (const float4*)sWa;
    const float4* wb4 = (const float4*)sWb;
    const float* hr = sh + nl * 64;
    const float* hnr = shn + nl * 64;

    #pragma unroll 4
    for (int k = 0; k < 64; k++) {
        float a = hr[k], b = hnr[k];
        float2 a2 = make_float2(a, a), b2 = make_float2(b, b);
        #pragma unroll
        for (int i = 0; i < 4; i++) {
            float4 wa = wa4[k * 16 + part * 4 + i];
            ffma2(acc[2 * i],     a2, make_float2(wa.x, wa.y));
            ffma2(acc[2 * i + 1], a2, make_float2(wa.z, wa.w));
            float4 wb = wb4[k * 16 + part * 4 + i];
            ffma2(acc[2 * i],     b2, make_float2(wb.x, wb.y));
            ffma2(acc[2 * i + 1], b2, make_float2(wb.z, wb.w));
        }
    }

    float s = 0.f;
    #pragma unroll
    for (int i = 0; i < 8; i++) {
        acc[i].x = fmaxf(acc[i].x, 0.f);
        acc[i].y = fmaxf(acc[i].y, 0.f);
        s = fmaf(acc[i].x, acc[i].x, s);
        s = fmaf(acc[i].y, acc[i].y, s);
    }
    s += __shfl_xor_sync(0xffffffffu, s, 1);
    s += __shfl_xor_sync(0xffffffffu, s, 2);
    float inv = 1.f / fmaxf(sqrtf(s), 1e-12f);

    float4* o4 = (float4*)(out + (base + nl) * 64 + part * 16);
    #pragma unroll
    for (int i = 0; i < 4; i++)
        o4[i] = make_float4(acc[2 * i].x * inv, acc[2 * i].y * inv,
                            acc[2 * i + 1].x * inv, acc[2 * i + 1].y * inv);
}

// ---------------- host orchestration: dual-stream fork/join ---------------
extern "C" void kernel_launch(void* const* d_in, const int* in_sizes, int n_in,
                              void* d_out, int out_size) {
    const int*   edge_row     = (const int*)d_in[0];
    const int*   edge_col     = (const int*)d_in[1];
    const int*   batch_assign = (const int*)d_in[2];
    const float* X            = (const float*)d_in[3];
    const float* Xs           = (const float*)d_in[4];
    const float* W1           = (const float*)d_in[5];
    const float* W2           = (const float*)d_in[6];
    const float* W3           = (const float*)d_in[7];
    const float* Wl           = (const float*)d_in[8];
    const float* bl           = (const float*)d_in[9];
    float* out = (float*)d_out;

    int nE = in_sizes[0];

    float *hA, *hB, *hsA, *hsB;
    __half *hhA, *hhB, *hnv, *Wah, *Wbh;
    int* rp;
    cudaGetSymbolAddress((void**)&hA,  g_hA);
    cudaGetSymbolAddress((void**)&hB,  g_hB);
    cudaGetSymbolAddress((void**)&hhA, g_hhA);
    cudaGetSymbolAddress((void**)&hhB, g_hhB);
    cudaGetSymbolAddress((void**)&hnv, g_hnv);
    cudaGetSymbolAddress((void**)&hsA, g_hsA);
    cudaGetSymbolAddress((void**)&hsB, g_hsB);
    cudaGetSymbolAddress((void**)&Wah, g_Wah);
    cudaGetSymbolAddress((void**)&Wbh, g_Wbh);
    cudaGetSymbolAddress((void**)&rp,  g_rowptr);

    cudaStream_t s1 = 0;   // capture (legacy) stream: node path
    cudaStream_t s2;       // batch path
    cudaStreamCreateWithFlags(&s2, cudaStreamNonBlocking);
    cudaEvent_t evFork, evEnd, evU[3], evP[3];
    cudaEventCreateWithFlags(&evFork, cudaEventDisableTiming);
    cudaEventCreateWithFlags(&evEnd,  cudaEventDisableTiming);
    for (int d = 0; d < 3; d++) {
        cudaEventCreateWithFlags(&evU[d], cudaEventDisableTiming);
        cudaEventCreateWithFlags(&evP[d], cudaEventDisableTiming);
    }

    int prep_blocks = 2 + INIT_BLKS + (nE + 255) / 256;
    prep<<<prep_blocks, 256, 0, s1>>>(edge_row, nE, X, Xs, W1, W2, W3, Wl,
                                      hA, hhA, hsA);
    cudaEventRecord(evFork, s1);
    cudaStreamWaitEvent(s2, evFork, 0);

    float* hc = hA;  float* hn_ = hB;
    __half* hhc = hhA; __half* hhn = hhB;
    float* hsc = hsA; float* hsn = hsB;
    for (int d = 0; d < 3; d++) {
        float* hout  = (d == 2) ? out : hn_;
        float* hsout = (d == 2) ? (out + N_NODES * D_EMB) : hsn;

        if (d == 0) {
            // host order: prep[2], spmm[3], pool_partial[4], update_h[5] -> ncu -s5
            spmm<<<(N_NODES * 32 + 255) / 256, 256, 0, s1>>>(
                (const __half2*)hhc, edge_col, rp, (__half2*)hnv);
            pool_partial<<<PB, 128, 0, s2>>>(hc, batch_assign, N_NODES);
            cudaEventRecord(evP[d], s2);
            update_h<<<(NPAD / UH_NODES), 128, 0, s1>>>(
                hhc, hnv, Wah, Wbh, bl, hout, hhn, N_NODES);
            cudaEventRecord(evU[d], s1);
            pool_reduce<<<16, 256, 0, s2>>>();
            update_hs<<<2, 128, 0, s2>>>(hsc, bl, hsout);
            cudaStreamWaitEvent(s2, evU[d], 0);  // next pool reads new h
        } else {
            spmm<<<(N_NODES * 32 + 255) / 256, 256, 0, s1>>>(
                (const __half2*)hhc, edge_col, rp, (__half2*)hnv);
            pool_partial<<<PB, 128, 0, s2>>>(hc, batch_assign, N_NODES);
            cudaEventRecord(evP[d], s2);
            pool_reduce<<<16, 256, 0, s2>>>();
            update_hs<<<2, 128, 0, s2>>>(hsc, bl, hsout);

            cudaStreamWaitEvent(s1, evP[d - 1], 0);
            update_h<<<(NPAD / UH_NODES), 128, 0, s1>>>(
                hhc, hnv, Wah, Wbh, bl, hout, hhn, N_NODES);
            cudaEventRecord(evU[d], s1);
            if (d < 2) cudaStreamWaitEvent(s2, evU[d], 0);
        }

        float* tf = hc; hc = hn_; hn_ = tf;
        __half* th = hhc; hhc = hhn; hhn = th;
        tf = hsc; hsc = hsn; hsn = tf;
    }

    cudaEventRecord(evEnd, s2);
    cudaStreamWaitEvent(s1, evEnd, 0);   // join: all output visible on s1
}

// round 10
// speedup vs baseline: 3.0114x; 1.3470x over previous
#include <cuda_runtime.h>
#include <cuda_fp16.h>
#include <cstdint>

#define N_NODES 50000
#define NPAD    50048
#define D_EMB   64
#define N_BATCH 64
#define PB      128   // pool partial blocks
#define UH_NODES 64   // nodes per update_h block
#define AST     136   // smem row stride in halves (272B = 17 uint4)

// ---------------- scratch (device globals; no allocation) ----------------
__device__ float  g_hA[NPAD * D_EMB];
__device__ float  g_hB[NPAD * D_EMB];
__device__ __half g_hhA[NPAD * D_EMB];
__device__ __half g_hhB[NPAD * D_EMB];
__device__ __half g_hnv[NPAD * D_EMB];          // fp16 spmm output
__device__ float  g_hsA[N_BATCH * D_EMB];
__device__ float  g_hsB[N_BATCH * D_EMB];
__device__ float  g_Wa[D_EMB * D_EMB];
__device__ float  g_Wb[D_EMB * D_EMB];
__device__ __half g_Wt[D_EMB * 2 * D_EMB];      // fused weights, [n=64][k=128] fp16
__device__ int    g_rowptr[N_NODES + 1];
__device__ float  g_pp[PB * N_BATCH * D_EMB];
__device__ float  g_ppq[4 * N_BATCH * D_EMB];

// ---------------- packed f32x2 FMA (update_hs only) -----------------------
union F2U { float2 f; unsigned long long u; };
__device__ __forceinline__ void ffma2(float2& c, float2 a, float2 b) {
    F2U A, B, C; A.f = a; B.f = b; C.f = c;
    asm("fma.rn.f32x2 %0, %1, %2, %0;" : "+l"(C.u) : "l"(A.u), "l"(B.u));
    c = C.f;
}

__device__ __forceinline__ uint32_t s2u(const void* p) {
    return (uint32_t)__cvta_generic_to_shared(p);
}

#define MMA16816(c0, c1, c2, c3, a0, a1, a2, a3, b0, b1)                       \
    asm volatile(                                                              \
        "mma.sync.aligned.m16n8k16.row.col.f32.f16.f16.f32 "                   \
        "{%0,%1,%2,%3}, {%4,%5,%6,%7}, {%8,%9}, {%0,%1,%2,%3};"                \
        : "+f"(c0), "+f"(c1), "+f"(c2), "+f"(c3)                               \
        : "r"(a0), "r"(a1), "r"(a2), "r"(a3), "r"(b0), "r"(b1))

// ---------------- prep: fuse_w + init_h + init_hs + rowptr, one launch ----
#define INIT_BLKS ((N_NODES + 255) / 256)

__global__ void prep(const int* __restrict__ er, int nE,
                     const float* __restrict__ X, const float* __restrict__ Xs,
                     const float* __restrict__ W1, const float* __restrict__ W2,
                     const float* __restrict__ W3, const float* __restrict__ Wl,
                     float* __restrict__ h, __half* __restrict__ hh,
                     float* __restrict__ hs) {
    __shared__ float sWl[8192];   // full Wl [128,64], 32 KB (block 0 only)
    int b = blockIdx.x, t = threadIdx.x;
    if (b == 0) {
        for (int i = t; i < 2048; i += 256)
            ((float4*)sWl)[i] = ((const float4*)Wl)[i];
        __syncthreads();
        for (int o = t; o < 4096; o += 256) {
            int i = o >> 6, j = o & 63;   // i = input dim (k), j = output dim (n)
            float sa = 0.f, sb = 0.f;
            #pragma unroll 8
            for (int k = 0; k < 64; k++) {
                sa = fmaf(W2[i * 64 + k], sWl[k * 64 + j], sa);
                sb = fmaf(W3[i * 64 + k], sWl[(64 + k) * 64 + j], sb);
            }
            g_Wa[o] = sa; g_Wb[o] = sb;
            g_Wt[j * 128 + i]      = __float2half(sa);   // Wt[n][k]      (h part)
            g_Wt[j * 128 + 64 + i] = __float2half(sb);   // Wt[n][64+k]   (hnv part)
        }
    } else if (b == 1) {
        if (t < N_BATCH) {
            float x0 = Xs[t * 2], x1 = Xs[t * 2 + 1];
            float s = 0.f;
            #pragma unroll
            for (int j = 0; j < 64; j++) {
                float v = fmaxf(fmaf(x0, W1[j], x1 * W1[64 + j]), 0.f);
                s = fmaf(v, v, s);
            }
            float inv = 1.f / fmaxf(sqrtf(s), 1e-12f);
            #pragma unroll
            for (int j = 0; j < 64; j++) {
                float v = fmaxf(fmaf(x0, W1[j], x1 * W1[64 + j]), 0.f);
                hs[t * 64 + j] = v * inv;
            }
        }
    } else if (b < 2 + INIT_BLKS) {
        int n = (b - 2) * 256 + t;
        if (n < N_NODES) {
            float x0 = X[n * 2], x1 = X[n * 2 + 1];
            float s = 0.f;
            #pragma unroll
            for (int j = 0; j < 64; j++) {
                float v = fmaxf(fmaf(x0, W1[j], x1 * W1[64 + j]), 0.f);
                s = fmaf(v, v, s);
            }
            float inv = 1.f / fmaxf(sqrtf(s), 1e-12f);
            float4* h4 = (float4*)(h + n * 64);
            __half2* hh2 = (__half2*)(hh + n * 64);
            #pragma unroll
            for (int j = 0; j < 64; j += 4) {
                float v0 = fmaxf(fmaf(x0, W1[j],     x1 * W1[64 + j]),     0.f) * inv;
                float v1 = fmaxf(fmaf(x0, W1[j + 1], x1 * W1[64 + j + 1]), 0.f) * inv;
                float v2 = fmaxf(fmaf(x0, W1[j + 2], x1 * W1[64 + j + 2]), 0.f) * inv;
                float v3 = fmaxf(fmaf(x0, W1[j + 3], x1 * W1[64 + j + 3]), 0.f) * inv;
                h4[j / 4] = make_float4(v0, v1, v2, v3);
                hh2[j / 2]     = __floats2half2_rn(v0, v1);
                hh2[j / 2 + 1] = __floats2half2_rn(v2, v3);
            }
        }
    } else {
        int e = (b - (2 + INIT_BLKS)) * 256 + t;
        if (e < nE) {
            int r = er[e];
            int rprev = (e == 0) ? -1 : er[e - 1];
            for (int rr = rprev + 1; rr <= r; rr++) g_rowptr[rr] = e;
            if (e == nE - 1)
                for (int rr = r + 1; rr <= N_NODES; rr++) g_rowptr[rr] = nE;
        }
    }
}

// ---------------- SPMM (fp16 gather, 16-deep MLP; fp16 output) ------------
__global__ void spmm(const __half2* __restrict__ hh, const int* __restrict__ col,
                     const int* __restrict__ rp, __half2* __restrict__ out) {
    int w = (blockIdx.x * blockDim.x + threadIdx.x) >> 5;
    if (w >= N_NODES) return;
    int lane = threadIdx.x & 31;
    int s = rp[w], e = rp[w + 1];
    float ax = 0.f, ay = 0.f, bx = 0.f, by = 0.f;
    int i = s;
    for (; i + 16 <= e; i += 16) {
        int c[16];
        #pragma unroll
        for (int u = 0; u < 16; u++) c[u] = __ldg(col + i + u);
        float2 v[16];
        #pragma unroll
        for (int u = 0; u < 16; u++) v[u] = __half22float2(hh[c[u] * 32 + lane]);
        #pragma unroll
        for (int u = 0; u < 16; u += 2) {
            ax += v[u].x;     ay += v[u].y;
            bx += v[u + 1].x; by += v[u + 1].y;
        }
    }
    for (; i + 4 <= e; i += 4) {
        int c0 = __ldg(col + i);
        int c1 = __ldg(col + i + 1);
        int c2 = __ldg(col + i + 2);
        int c3 = __ldg(col + i + 3);
        float2 v0 = __half22float2(hh[c0 * 32 + lane]);
        float2 v1 = __half22float2(hh[c1 * 32 + lane]);
        float2 v2 = __half22float2(hh[c2 * 32 + lane]);
        float2 v3 = __half22float2(hh[c3 * 32 + lane]);
        ax += v0.x + v2.x; ay += v0.y + v2.y;
        bx += v1.x + v3.x; by += v1.y + v3.y;
    }
    for (; i < e; i++) {
        float2 v = __half22float2(hh[__ldg(col + i) * 32 + lane]);
        ax += v.x; ay += v.y;
    }
    out[w * 32 + lane] = __floats2half2_rn(ax + bx, ay + by);
}

// ---------------- batch pooling stage 1 (deterministic, no atomics) -------
__global__ void __launch_bounds__(128) pool_partial(const float* __restrict__ h,
                                                    const int* __restrict__ ba, int n) {
    __shared__ float acc[2 * N_BATCH * D_EMB];  // 32 KB
    int t = threadIdx.x;
    for (int i = t; i < 2 * 4096; i += 128) acc[i] = 0.f;
    __syncthreads();
    int per = (n + PB - 1) / PB;
    int start = blockIdx.x * per;
    int end = min(start + per, n);
    int j = t & 63;
    int nl = t >> 6;
    float* my = acc + nl * 4096;
    for (int nn = start + nl; nn < end; nn += 2) {
        int b = ba[nn];
        my[b * 64 + j] += h[nn * 64 + j];
    }
    __syncthreads();
    for (int i = t; i < 4096; i += 128)
        g_pp[blockIdx.x * 4096 + i] = acc[i] + acc[4096 + i];
}

// ---------------- pooling stage 2: 4096 threads, float4, 4-way K-split ----
__global__ void pool_reduce() {
    int tid = blockIdx.x * blockDim.x + threadIdx.x;  // 4096
    int q = tid >> 10, i4 = tid & 1023;
    const float4* pp = (const float4*)g_pp;
    float4 s = make_float4(0.f, 0.f, 0.f, 0.f);
    #pragma unroll 8
    for (int b = q * 32; b < q * 32 + 32; b++) {
        float4 v = pp[b * 1024 + i4];
        s.x += v.x; s.y += v.y; s.z += v.z; s.w += v.w;
    }
    ((float4*)g_ppq)[q * 1024 + i4] = s;
}

// ---------------- update_h v4: tensor-core HMMA (m16n8k16) ----------------
// C[64x64] = [h|hnv][64x128] @ Wt^T ; bias in C init; relu+l2norm epilogue.
__global__ void __launch_bounds__(128, 6) update_h(
    const __half* __restrict__ hhin, const __half* __restrict__ hnv,
    const __half* __restrict__ Wt, const float* __restrict__ bl,
    float* __restrict__ out, __half* __restrict__ hho, int nrows) {
    __shared__ __half sA[64 * AST];   // A tile [node][k], 17408 B
    __shared__ __half sW[64 * AST];   // Wt     [n][k],    17408 B
    int t = threadIdx.x;
    int base = blockIdx.x * UH_NODES;
    for (int i = t; i < 1024; i += 128) {
        int r = i >> 4, c = i & 15;
        uint4 v = (c < 8)
            ? ((const uint4*)(hhin + (size_t)(base + r) * 64))[c]
            : ((const uint4*)(hnv + (size_t)(base + r) * 64))[c - 8];
        ((uint4*)sA)[r * 17 + c] = v;
        ((uint4*)sW)[r * 17 + c] = ((const uint4*)(Wt + r * 128))[c];
    }
    __syncthreads();

    int wid = t >> 5, lane = t & 31;
    int g = lane >> 2, tg = lane & 3;
    int m0 = wid * 16;

    float c0[8], c1[8], c2[8], c3[8];
    #pragma unroll
    for (int j = 0; j < 8; j++) {
        float b0 = bl[j * 8 + 2 * tg];
        float b1 = bl[j * 8 + 2 * tg + 1];
        c0[j] = b0; c1[j] = b1; c2[j] = b0; c3[j] = b1;
    }

    int mat = lane >> 3, mlow = lane & 7;
    #pragma unroll
    for (int ks = 0; ks < 8; ks++) {
        int k0 = ks * 16;
        uint32_t a0, a1, a2, a3;
        {
            int row = m0 + (mat & 1) * 8 + mlow;
            int col = k0 + (mat >> 1) * 8;
            uint32_t addr = s2u(sA + row * AST + col);
            asm volatile(
                "ldmatrix.sync.aligned.m8n8.x4.shared.b16 {%0,%1,%2,%3}, [%4];"
                : "=r"(a0), "=r"(a1), "=r"(a2), "=r"(a3) : "r"(addr));
        }
        #pragma unroll
        for (int jp = 0; jp < 4; jp++) {
            uint32_t b0, b1, b2, b3;
            int nrow = (jp * 2 + (mat >> 1)) * 8 + mlow;
            int kc = k0 + (mat & 1) * 8;
            uint32_t addr = s2u(sW + nrow * AST + kc);
            asm volatile(
                "ldmatrix.sync.aligned.m8n8.x4.shared.b16 {%0,%1,%2,%3}, [%4];"
                : "=r"(b0), "=r"(b1), "=r"(b2), "=r"(b3) : "r"(addr));
            int j = jp * 2;
            MMA16816(c0[j], c1[j], c2[j], c3[j], a0, a1, a2, a3, b0, b1);
            MMA16816(c0[j + 1], c1[j + 1], c2[j + 1], c3[j + 1],
                     a0, a1, a2, a3, b2, b3);
        }
    }

    // relu + per-row sum of squares (row A = m0+g, row B = m0+g+8)
    float sa2 = 0.f, sb2 = 0.f;
    #pragma unroll
    for (int j = 0; j < 8; j++) {
        c0[j] = fmaxf(c0[j], 0.f); c1[j] = fmaxf(c1[j], 0.f);
        c2[j] = fmaxf(c2[j], 0.f); c3[j] = fmaxf(c3[j], 0.f);
        sa2 = fmaf(c0[j], c0[j], sa2); sa2 = fmaf(c1[j], c1[j], sa2);
        sb2 = fmaf(c2[j], c2[j], sb2); sb2 = fmaf(c3[j], c3[j], sb2);
    }
    sa2 += __shfl_xor_sync(0xffffffffu, sa2, 1);
    sa2 += __shfl_xor_sync(0xffffffffu, sa2, 2);
    sb2 += __shfl_xor_sync(0xffffffffu, sb2, 1);
    sb2 += __shfl_xor_sync(0xffffffffu, sb2, 2);
    float invA = 1.f / fmaxf(sqrtf(sa2), 1e-12f);
    float invB = 1.f / fmaxf(sqrtf(sb2), 1e-12f);

    int nA = base + m0 + g, nB = nA + 8;
    if (nA < nrows) {
        #pragma unroll
        for (int j = 0; j < 8; j++) {
            float x = c0[j] * invA, y = c1[j] * invA;
            *(float2*)(out + (size_t)nA * 64 + j * 8 + 2 * tg) = make_float2(x, y);
            *(__half2*)(hho + (size_t)nA * 64 + j * 8 + 2 * tg) =
                __floats2half2_rn(x, y);
        }
    }
    if (nB < nrows) {
        #pragma unroll
        for (int j = 0; j < 8; j++) {
            float x = c2[j] * invB, y = c3[j] * invB;
            *(float2*)(out + (size_t)nB * 64 + j * 8 + 2 * tg) = make_float2(x, y);
            *(__half2*)(hho + (size_t)nB * 64 + j * 8 + 2 * tg) =
                __floats2half2_rn(x, y);
        }
    }
}

// ---------------- batch update (folds 4-quarter reduce) -------------------
__global__ void __launch_bounds__(128) update_hs(
    const float* __restrict__ hs, const float* __restrict__ bl,
    float* __restrict__ out) {
    __shared__ float sWa[4096], sWb[4096];
    __shared__ float sh[2048], shn[2048];
    int t = threadIdx.x;
    int base = blockIdx.x * 32;
    for (int i = t; i < 1024; i += 128) {
        ((float4*)sWa)[i] = ((const float4*)g_Wa)[i];
        ((float4*)sWb)[i] = ((const float4*)g_Wb)[i];
    }
    for (int i = t; i < 512; i += 128)
        ((float4*)sh)[i] = ((const float4*)(hs + base * 64))[i];
    for (int i = t; i < 512; i += 128) {
        float4 s = make_float4(0.f, 0.f, 0.f, 0.f);
        #pragma unroll
        for (int q = 0; q < 4; q++) {
            float4 v = ((const float4*)g_ppq)[q * 1024 + base * 16 + i];
            s.x += v.x; s.y += v.y; s.z += v.z; s.w += v.w;
        }
        ((float4*)shn)[i] = s;
    }
    __syncthreads();

    int nl = t >> 2, part = t & 3;
    float2 acc[8];
    #pragma unroll
    for (int i = 0; i < 8; i++) acc[i] = ((const float2*)bl)[part * 8 + i];

    const float4* wa4 = (const float4*)sWa;
    const float4* wb4 = (const float4*)sWb;
    const float* hr = sh + nl * 64;
    const float* hnr = shn + nl * 64;

    #pragma unroll 4
    for (int k = 0; k < 64; k++) {
        float a = hr[k], b = hnr[k];
        float2 a2 = make_float2(a, a), b2 = make_float2(b, b);
        #pragma unroll
        for (int i = 0; i < 4; i++) {
            float4 wa = wa4[k * 16 + part * 4 + i];
            ffma2(acc[2 * i],     a2, make_float2(wa.x, wa.y));
            ffma2(acc[2 * i + 1], a2, make_float2(wa.z, wa.w));
            float4 wb = wb4[k * 16 + part * 4 + i];
            ffma2(acc[2 * i],     b2, make_float2(wb.x, wb.y));
            ffma2(acc[2 * i + 1], b2, make_float2(wb.z, wb.w));
        }
    }

    float s = 0.f;
    #pragma unroll
    for (int i = 0; i < 8; i++) {
        acc[i].x = fmaxf(acc[i].x, 0.f);
        acc[i].y = fmaxf(acc[i].y, 0.f);
        s = fmaf(acc[i].x, acc[i].x, s);
        s = fmaf(acc[i].y, acc[i].y, s);
    }
    s += __shfl_xor_sync(0xffffffffu, s, 1);
    s += __shfl_xor_sync(0xffffffffu, s, 2);
    float inv = 1.f / fmaxf(sqrtf(s), 1e-12f);

    float4* o4 = (float4*)(out + (base + nl) * 64 + part * 16);
    #pragma unroll
    for (int i = 0; i < 4; i++)
        o4[i] = make_float4(acc[2 * i].x * inv, acc[2 * i].y * inv,
                            acc[2 * i + 1].x * inv, acc[2 * i + 1].y * inv);
}

// ---------------- host orchestration: dual-stream fork/join ---------------
extern "C" void kernel_launch(void* const* d_in, const int* in_sizes, int n_in,
                              void* d_out, int out_size) {
    const int*   edge_row     = (const int*)d_in[0];
    const int*   edge_col     = (const int*)d_in[1];
    const int*   batch_assign = (const int*)d_in[2];
    const float* X            = (const float*)d_in[3];
    const float* Xs           = (const float*)d_in[4];
    const float* W1           = (const float*)d_in[5];
    const float* W2           = (const float*)d_in[6];
    const float* W3           = (const float*)d_in[7];
    const float* Wl           = (const float*)d_in[8];
    const float* bl           = (const float*)d_in[9];
    float* out = (float*)d_out;

    int nE = in_sizes[0];

    float *hA, *hB, *hsA, *hsB;
    __half *hhA, *hhB, *hnv, *Wt;
    int* rp;
    cudaGetSymbolAddress((void**)&hA,  g_hA);
    cudaGetSymbolAddress((void**)&hB,  g_hB);
    cudaGetSymbolAddress((void**)&hhA, g_hhA);
    cudaGetSymbolAddress((void**)&hhB, g_hhB);
    cudaGetSymbolAddress((void**)&hnv, g_hnv);
    cudaGetSymbolAddress((void**)&hsA, g_hsA);
    cudaGetSymbolAddress((void**)&hsB, g_hsB);
    cudaGetSymbolAddress((void**)&Wt,  g_Wt);
    cudaGetSymbolAddress((void**)&rp,  g_rowptr);

    cudaStream_t s1 = 0;   // capture (legacy) stream: node path
    cudaStream_t s2;       // batch path
    cudaStreamCreateWithFlags(&s2, cudaStreamNonBlocking);
    cudaEvent_t evFork, evEnd, evU[3], evP[3];
    cudaEventCreateWithFlags(&evFork, cudaEventDisableTiming);
    cudaEventCreateWithFlags(&evEnd,  cudaEventDisableTiming);
    for (int d = 0; d < 3; d++) {
        cudaEventCreateWithFlags(&evU[d], cudaEventDisableTiming);
        cudaEventCreateWithFlags(&evP[d], cudaEventDisableTiming);
    }

    int prep_blocks = 2 + INIT_BLKS + (nE + 255) / 256;
    prep<<<prep_blocks, 256, 0, s1>>>(edge_row, nE, X, Xs, W1, W2, W3, Wl,
                                      hA, hhA, hsA);
    cudaEventRecord(evFork, s1);
    cudaStreamWaitEvent(s2, evFork, 0);

    float* hc = hA;  float* hn_ = hB;
    __half* hhc = hhA; __half* hhn = hhB;
    float* hsc = hsA; float* hsn = hsB;
    for (int d = 0; d < 3; d++) {
        float* hout  = (d == 2) ? out : hn_;
        float* hsout = (d == 2) ? (out + N_NODES * D_EMB) : hsn;

        if (d == 0) {
            // host order: prep[2], spmm[3], pool_partial[4], update_h[5] -> ncu -s5
            spmm<<<(N_NODES * 32 + 255) / 256, 256, 0, s1>>>(
                (const __half2*)hhc, edge_col, rp, (__half2*)hnv);
            pool_partial<<<PB, 128, 0, s2>>>(hc, batch_assign, N_NODES);
            cudaEventRecord(evP[d], s2);
            update_h<<<(NPAD / UH_NODES), 128, 0, s1>>>(
                hhc, hnv, Wt, bl, hout, hhn, N_NODES);
            cudaEventRecord(evU[d], s1);
            pool_reduce<<<16, 256, 0, s2>>>();
            update_hs<<<2, 128, 0, s2>>>(hsc, bl, hsout);
            cudaStreamWaitEvent(s2, evU[d], 0);  // next pool reads new h
        } else {
            spmm<<<(N_NODES * 32 + 255) / 256, 256, 0, s1>>>(
                (const __half2*)hhc, edge_col, rp, (__half2*)hnv);
            pool_partial<<<PB, 128, 0, s2>>>(hc, batch_assign, N_NODES);
            cudaEventRecord(evP[d], s2);
            pool_reduce<<<16, 256, 0, s2>>>();
            update_hs<<<2, 128, 0, s2>>>(hsc, bl, hsout);

            cudaStreamWaitEvent(s1, evP[d - 1], 0);
            update_h<<<(NPAD / UH_NODES), 128, 0, s1>>>(
                hhc, hnv, Wt, bl, hout, hhn, N_NODES);
            cudaEventRecord(evU[d], s1);
            if (d < 2) cudaStreamWaitEvent(s2, evU[d], 0);
        }

        float* tf = hc; hc = hn_; hn_ = tf;
        __half* th = hhc; hhc = hhn; hhn = th;
        tf = hsc; hsc = hsn; hsn = tf;
    }

    cudaEventRecord(evEnd, s2);
    cudaStreamWaitEvent(s1, evEnd, 0);   // join: all output visible on s1
}

// round 11
// speedup vs baseline: 3.6262x; 1.2042x over previous
#include <cuda_runtime.h>
#include <cuda_fp16.h>
#include <cstdint>

#define N_NODES 50000
#define NPAD    50048
#define D_EMB   64
#define N_BATCH 64
#define PB      128   // pool partial blocks
#define UH_NODES 64   // nodes per update_h block
#define AST     136   // smem row stride in halves (272B = 17 uint4)

// ---------------- scratch (device globals; no allocation) ----------------
__device__ __half g_hh0[NPAD * D_EMB];          // fp16 h, triple-buffered
__device__ __half g_hh1[NPAD * D_EMB];
__device__ __half g_hh2[NPAD * D_EMB];
__device__ __half g_hnv[NPAD * D_EMB];          // fp16 spmm output
__device__ float  g_hsA[N_BATCH * D_EMB];
__device__ float  g_hsB[N_BATCH * D_EMB];
__device__ float  g_Wa[D_EMB * D_EMB];
__device__ float  g_Wb[D_EMB * D_EMB];
__device__ __half g_Wt[D_EMB * 2 * D_EMB];      // fused weights, [n=64][k=128] fp16
__device__ int    g_rowptr[N_NODES + 1];
__device__ float  g_pp[PB * N_BATCH * D_EMB];
__device__ float  g_ppq[4 * N_BATCH * D_EMB];

// ---------------- packed f32x2 FMA (update_hs only) -----------------------
union F2U { float2 f; unsigned long long u; };
__device__ __forceinline__ void ffma2(float2& c, float2 a, float2 b) {
    F2U A, B, C; A.f = a; B.f = b; C.f = c;
    asm("fma.rn.f32x2 %0, %1, %2, %0;" : "+l"(C.u) : "l"(A.u), "l"(B.u));
    c = C.f;
}

__device__ __forceinline__ uint32_t s2u(const void* p) {
    return (uint32_t)__cvta_generic_to_shared(p);
}

#define MMA16816(c0, c1, c2, c3, a0, a1, a2, a3, b0, b1)                       \
    asm volatile(                                                              \
        "mma.sync.aligned.m16n8k16.row.col.f32.f16.f16.f32 "                   \
        "{%0,%1,%2,%3}, {%4,%5,%6,%7}, {%8,%9}, {%0,%1,%2,%3};"                \
        : "+f"(c0), "+f"(c1), "+f"(c2), "+f"(c3)                               \
        : "r"(a0), "r"(a1), "r"(a2), "r"(a3), "r"(b0), "r"(b1))

// ---------------- prep: fuse_w + init_h + init_hs + rowptr, one launch ----
#define INIT_BLKS ((N_NODES + 255) / 256)

__global__ void prep(const int* __restrict__ er, int nE,
                     const float* __restrict__ X, const float* __restrict__ Xs,
                     const float* __restrict__ W1, const float* __restrict__ W2,
                     const float* __restrict__ W3, const float* __restrict__ Wl,
                     __half* __restrict__ hh, float* __restrict__ hs) {
    __shared__ float sWl[8192];   // full Wl [128,64], 32 KB (block 0 only)
    int b = blockIdx.x, t = threadIdx.x;
    if (b == 0) {
        for (int i = t; i < 2048; i += 256)
            ((float4*)sWl)[i] = ((const float4*)Wl)[i];
        __syncthreads();
        for (int o = t; o < 4096; o += 256) {
            int i = o >> 6, j = o & 63;   // i = input dim (k), j = output dim (n)
            float sa = 0.f, sb = 0.f;
            #pragma unroll 8
            for (int k = 0; k < 64; k++) {
                sa = fmaf(W2[i * 64 + k], sWl[k * 64 + j], sa);
                sb = fmaf(W3[i * 64 + k], sWl[(64 + k) * 64 + j], sb);
            }
            g_Wa[o] = sa; g_Wb[o] = sb;
            g_Wt[j * 128 + i]      = __float2half(sa);   // Wt[n][k]      (h part)
            g_Wt[j * 128 + 64 + i] = __float2half(sb);   // Wt[n][64+k]   (hnv part)
        }
    } else if (b == 1) {
        if (t < N_BATCH) {
            float x0 = Xs[t * 2], x1 = Xs[t * 2 + 1];
            float s = 0.f;
            #pragma unroll
            for (int j = 0; j < 64; j++) {
                float v = fmaxf(fmaf(x0, W1[j], x1 * W1[64 + j]), 0.f);
                s = fmaf(v, v, s);
            }
            float inv = 1.f / fmaxf(sqrtf(s), 1e-12f);
            #pragma unroll
            for (int j = 0; j < 64; j++) {
                float v = fmaxf(fmaf(x0, W1[j], x1 * W1[64 + j]), 0.f);
                hs[t * 64 + j] = v * inv;
            }
        }
    } else if (b < 2 + INIT_BLKS) {
        int n = (b - 2) * 256 + t;
        if (n < N_NODES) {
            float x0 = X[n * 2], x1 = X[n * 2 + 1];
            float s = 0.f;
            #pragma unroll
            for (int j = 0; j < 64; j++) {
                float v = fmaxf(fmaf(x0, W1[j], x1 * W1[64 + j]), 0.f);
                s = fmaf(v, v, s);
            }
            float inv = 1.f / fmaxf(sqrtf(s), 1e-12f);
            __half2* hh2 = (__half2*)(hh + (size_t)n * 64);
            #pragma unroll
            for (int j = 0; j < 64; j += 2) {
                float v0 = fmaxf(fmaf(x0, W1[j],     x1 * W1[64 + j]),     0.f) * inv;
                float v1 = fmaxf(fmaf(x0, W1[j + 1], x1 * W1[64 + j + 1]), 0.f) * inv;
                hh2[j / 2] = __floats2half2_rn(v0, v1);
            }
        }
    } else {
        int e = (b - (2 + INIT_BLKS)) * 256 + t;
        if (e < nE) {
            int r = er[e];
            int rprev = (e == 0) ? -1 : er[e - 1];
            for (int rr = rprev + 1; rr <= r; rr++) g_rowptr[rr] = e;
            if (e == nE - 1)
                for (int rr = r + 1; rr <= N_NODES; rr++) g_rowptr[rr] = nE;
        }
    }
}

// ---------------- SPMM (fp16 gather, 16-deep MLP; fp16 output) ------------
__global__ void spmm(const __half2* __restrict__ hh, const int* __restrict__ col,
                     const int* __restrict__ rp, __half2* __restrict__ out) {
    int w = (blockIdx.x * blockDim.x + threadIdx.x) >> 5;
    if (w >= N_NODES) return;
    int lane = threadIdx.x & 31;
    int s = rp[w], e = rp[w + 1];
    float ax = 0.f, ay = 0.f, bx = 0.f, by = 0.f;
    int i = s;
    for (; i + 16 <= e; i += 16) {
        int c[16];
        #pragma unroll
        for (int u = 0; u < 16; u++) c[u] = __ldg(col + i + u);
        float2 v[16];
        #pragma unroll
        for (int u = 0; u < 16; u++) v[u] = __half22float2(hh[c[u] * 32 + lane]);
        #pragma unroll
        for (int u = 0; u < 16; u += 2) {
            ax += v[u].x;     ay += v[u].y;
            bx += v[u + 1].x; by += v[u + 1].y;
        }
    }
    for (; i + 4 <= e; i += 4) {
        int c0 = __ldg(col + i);
        int c1 = __ldg(col + i + 1);
        int c2 = __ldg(col + i + 2);
        int c3 = __ldg(col + i + 3);
        float2 v0 = __half22float2(hh[c0 * 32 + lane]);
        float2 v1 = __half22float2(hh[c1 * 32 + lane]);
        float2 v2 = __half22float2(hh[c2 * 32 + lane]);
        float2 v3 = __half22float2(hh[c3 * 32 + lane]);
        ax += v0.x + v2.x; ay += v0.y + v2.y;
        bx += v1.x + v3.x; by += v1.y + v3.y;
    }
    for (; i < e; i++) {
        float2 v = __half22float2(hh[__ldg(col + i) * 32 + lane]);
        ax += v.x; ay += v.y;
    }
    out[w * 32 + lane] = __floats2half2_rn(ax + bx, ay + by);
}

// ---------------- batch pooling stage 1 (fp16 input, deterministic) -------
__global__ void __launch_bounds__(128) pool_partial(const __half* __restrict__ h,
                                                    const int* __restrict__ ba, int n) {
    __shared__ float acc[2 * N_BATCH * D_EMB];  // 32 KB
    int t = threadIdx.x;
    for (int i = t; i < 2 * 4096; i += 128) acc[i] = 0.f;
    __syncthreads();
    int per = (n + PB - 1) / PB;
    int start = blockIdx.x * per;
    int end = min(start + per, n);
    int j = t & 63;
    int nl = t >> 6;
    float* my = acc + nl * 4096;
    for (int nn = start + nl; nn < end; nn += 2) {
        int b = ba[nn];
        my[b * 64 + j] += __half2float(h[(size_t)nn * 64 + j]);
    }
    __syncthreads();
    for (int i = t; i < 4096; i += 128)
        g_pp[blockIdx.x * 4096 + i] = acc[i] + acc[4096 + i];
}

// ---------------- pooling stage 2: 4096 threads, float4, 4-way K-split ----
__global__ void pool_reduce() {
    int tid = blockIdx.x * blockDim.x + threadIdx.x;  // 4096
    int q = tid >> 10, i4 = tid & 1023;
    const float4* pp = (const float4*)g_pp;
    float4 s = make_float4(0.f, 0.f, 0.f, 0.f);
    #pragma unroll 8
    for (int b = q * 32; b < q * 32 + 32; b++) {
        float4 v = pp[b * 1024 + i4];
        s.x += v.x; s.y += v.y; s.z += v.z; s.w += v.w;
    }
    ((float4*)g_ppq)[q * 1024 + i4] = s;
}

// ---------------- update_h: tensor-core HMMA (m16n8k16) -------------------
// mode 0: store fp16 h only; mode 1: store fp32 out only (final iter).
__global__ void __launch_bounds__(128, 6) update_h(
    const __half* __restrict__ hhin, const __half* __restrict__ hnv,
    const __half* __restrict__ Wt, const float* __restrict__ bl,
    float* __restrict__ out, __half* __restrict__ hho, int nrows, int mode) {
    __shared__ __half sA[64 * AST];   // A tile [node][k], 17408 B
    __shared__ __half sW[64 * AST];   // Wt     [n][k],    17408 B
    int t = threadIdx.x;
    int base = blockIdx.x * UH_NODES;
    for (int i = t; i < 1024; i += 128) {
        int r = i >> 4, c = i & 15;
        uint4 v = (c < 8)
            ? ((const uint4*)(hhin + (size_t)(base + r) * 64))[c]
            : ((const uint4*)(hnv + (size_t)(base + r) * 64))[c - 8];
        ((uint4*)sA)[r * 17 + c] = v;
        ((uint4*)sW)[r * 17 + c] = ((const uint4*)(Wt + r * 128))[c];
    }
    __syncthreads();

    int wid = t >> 5, lane = t & 31;
    int g = lane >> 2, tg = lane & 3;
    int m0 = wid * 16;

    float c0[8], c1[8], c2[8], c3[8];
    #pragma unroll
    for (int j = 0; j < 8; j++) {
        float b0 = bl[j * 8 + 2 * tg];
        float b1 = bl[j * 8 + 2 * tg + 1];
        c0[j] = b0; c1[j] = b1; c2[j] = b0; c3[j] = b1;
    }

    int mat = lane >> 3, mlow = lane & 7;
    #pragma unroll
    for (int ks = 0; ks < 8; ks++) {
        int k0 = ks * 16;
        uint32_t a0, a1, a2, a3;
        {
            int row = m0 + (mat & 1) * 8 + mlow;
            int col = k0 + (mat >> 1) * 8;
            uint32_t addr = s2u(sA + row * AST + col);
            asm volatile(
                "ldmatrix.sync.aligned.m8n8.x4.shared.b16 {%0,%1,%2,%3}, [%4];"
                : "=r"(a0), "=r"(a1), "=r"(a2), "=r"(a3) : "r"(addr));
        }
        #pragma unroll
        for (int jp = 0; jp < 4; jp++) {
            uint32_t b0, b1, b2, b3;
            int nrow = (jp * 2 + (mat >> 1)) * 8 + mlow;
            int kc = k0 + (mat & 1) * 8;
            uint32_t addr = s2u(sW + nrow * AST + kc);
            asm volatile(
                "ldmatrix.sync.aligned.m8n8.x4.shared.b16 {%0,%1,%2,%3}, [%4];"
                : "=r"(b0), "=r"(b1), "=r"(b2), "=r"(b3) : "r"(addr));
            int j = jp * 2;
            MMA16816(c0[j], c1[j], c2[j], c3[j], a0, a1, a2, a3, b0, b1);
            MMA16816(c0[j + 1], c1[j + 1], c2[j + 1], c3[j + 1],
                     a0, a1, a2, a3, b2, b3);
        }
    }

    // relu + per-row sum of squares (row A = m0+g, row B = m0+g+8)
    float sa2 = 0.f, sb2 = 0.f;
    #pragma unroll
    for (int j = 0; j < 8; j++) {
        c0[j] = fmaxf(c0[j], 0.f); c1[j] = fmaxf(c1[j], 0.f);
        c2[j] = fmaxf(c2[j], 0.f); c3[j] = fmaxf(c3[j], 0.f);
        sa2 = fmaf(c0[j], c0[j], sa2); sa2 = fmaf(c1[j], c1[j], sa2);
        sb2 = fmaf(c2[j], c2[j], sb2); sb2 = fmaf(c3[j], c3[j], sb2);
    }
    sa2 += __shfl_xor_sync(0xffffffffu, sa2, 1);
    sa2 += __shfl_xor_sync(0xffffffffu, sa2, 2);
    sb2 += __shfl_xor_sync(0xffffffffu, sb2, 1);
    sb2 += __shfl_xor_sync(0xffffffffu, sb2, 2);
    float invA = 1.f / fmaxf(sqrtf(sa2), 1e-12f);
    float invB = 1.f / fmaxf(sqrtf(sb2), 1e-12f);

    int nA = base + m0 + g, nB = nA + 8;
    if (mode == 0) {
        if (nA < nrows) {
            #pragma unroll
            for (int j = 0; j < 8; j++)
                *(__half2*)(hho + (size_t)nA * 64 + j * 8 + 2 * tg) =
                    __floats2half2_rn(c0[j] * invA, c1[j] * invA);
        }
        if (nB < nrows) {
            #pragma unroll
            for (int j = 0; j < 8; j++)
                *(__half2*)(hho + (size_t)nB * 64 + j * 8 + 2 * tg) =
                    __floats2half2_rn(c2[j] * invB, c3[j] * invB);
        }
    } else {
        if (nA < nrows) {
            #pragma unroll
            for (int j = 0; j < 8; j++)
                *(float2*)(out + (size_t)nA * 64 + j * 8 + 2 * tg) =
                    make_float2(c0[j] * invA, c1[j] * invA);
        }
        if (nB < nrows) {
            #pragma unroll
            for (int j = 0; j < 8; j++)
                *(float2*)(out + (size_t)nB * 64 + j * 8 + 2 * tg) =
                    make_float2(c2[j] * invB, c3[j] * invB);
        }
    }
}

// ---------------- batch update (folds 4-quarter reduce) -------------------
__global__ void __launch_bounds__(128) update_hs(
    const float* __restrict__ hs, const float* __restrict__ bl,
    float* __restrict__ out) {
    __shared__ float sWa[4096], sWb[4096];
    __shared__ float sh[2048], shn[2048];
    int t = threadIdx.x;
    int base = blockIdx.x * 32;
    for (int i = t; i < 1024; i += 128) {
        ((float4*)sWa)[i] = ((const float4*)g_Wa)[i];
        ((float4*)sWb)[i] = ((const float4*)g_Wb)[i];
    }
    for (int i = t; i < 512; i += 128)
        ((float4*)sh)[i] = ((const float4*)(hs + base * 64))[i];
    for (int i = t; i < 512; i += 128) {
        float4 s = make_float4(0.f, 0.f, 0.f, 0.f);
        #pragma unroll
        for (int q = 0; q < 4; q++) {
            float4 v = ((const float4*)g_ppq)[q * 1024 + base * 16 + i];
            s.x += v.x; s.y += v.y; s.z += v.z; s.w += v.w;
        }
        ((float4*)shn)[i] = s;
    }
    __syncthreads();

    int nl = t >> 2, part = t & 3;
    float2 acc[8];
    #pragma unroll
    for (int i = 0; i < 8; i++) acc[i] = ((const float2*)bl)[part * 8 + i];

    const float4* wa4 = (const float4*)sWa;
    const float4* wb4 = (const float4*)sWb;
    const float* hr = sh + nl * 64;
    const float* hnr = shn + nl * 64;

    #pragma unroll 4
    for (int k = 0; k < 64; k++) {
        float a = hr[k], b = hnr[k];
        float2 a2 = make_float2(a, a), b2 = make_float2(b, b);
        #pragma unroll
        for (int i = 0; i < 4; i++) {
            float4 wa = wa4[k * 16 + part * 4 + i];
            ffma2(acc[2 * i],     a2, make_float2(wa.x, wa.y));
            ffma2(acc[2 * i + 1], a2, make_float2(wa.z, wa.w));
            float4 wb = wb4[k * 16 + part * 4 + i];
            ffma2(acc[2 * i],     b2, make_float2(wb.x, wb.y));
            ffma2(acc[2 * i + 1], b2, make_float2(wb.z, wb.w));
        }
    }

    float s = 0.f;
    #pragma unroll
    for (int i = 0; i < 8; i++) {
        acc[i].x = fmaxf(acc[i].x, 0.f);
        acc[i].y = fmaxf(acc[i].y, 0.f);
        s = fmaf(acc[i].x, acc[i].x, s);
        s = fmaf(acc[i].y, acc[i].y, s);
    }
    s += __shfl_xor_sync(0xffffffffu, s, 1);
    s += __shfl_xor_sync(0xffffffffu, s, 2);
    float inv = 1.f / fmaxf(sqrtf(s), 1e-12f);

    float4* o4 = (float4*)(out + (base + nl) * 64 + part * 16);
    #pragma unroll
    for (int i = 0; i < 4; i++)
        o4[i] = make_float4(acc[2 * i].x * inv, acc[2 * i].y * inv,
                            acc[2 * i + 1].x * inv, acc[2 * i + 1].y * inv);
}

// ---------------- host orchestration: dual-stream, triple-buffered hh -----
extern "C" void kernel_launch(void* const* d_in, const int* in_sizes, int n_in,
                              void* d_out, int out_size) {
    const int*   edge_row     = (const int*)d_in[0];
    const int*   edge_col     = (const int*)d_in[1];
    const int*   batch_assign = (const int*)d_in[2];
    const float* X            = (const float*)d_in[3];
    const float* Xs           = (const float*)d_in[4];
    const float* W1           = (const float*)d_in[5];
    const float* W2           = (const float*)d_in[6];
    const float* W3           = (const float*)d_in[7];
    const float* Wl           = (const float*)d_in[8];
    const float* bl           = (const float*)d_in[9];
    float* out = (float*)d_out;

    int nE = in_sizes[0];

    float *hsA, *hsB;
    __half *hh0, *hh1, *hh2, *hnv, *Wt;
    int* rp;
    cudaGetSymbolAddress((void**)&hh0, g_hh0);
    cudaGetSymbolAddress((void**)&hh1, g_hh1);
    cudaGetSymbolAddress((void**)&hh2, g_hh2);
    cudaGetSymbolAddress((void**)&hnv, g_hnv);
    cudaGetSymbolAddress((void**)&hsA, g_hsA);
    cudaGetSymbolAddress((void**)&hsB, g_hsB);
    cudaGetSymbolAddress((void**)&Wt,  g_Wt);
    cudaGetSymbolAddress((void**)&rp,  g_rowptr);
    __half* hhbuf[3] = {hh0, hh1, hh2};

    cudaStream_t s1 = 0;   // capture (legacy) stream: node path
    cudaStream_t s2;       // batch path
    cudaStreamCreateWithFlags(&s2, cudaStreamNonBlocking);
    cudaEvent_t evFork, evEnd, evU[2], evP0;
    cudaEventCreateWithFlags(&evFork, cudaEventDisableTiming);
    cudaEventCreateWithFlags(&evEnd,  cudaEventDisableTiming);
    cudaEventCreateWithFlags(&evU[0], cudaEventDisableTiming);
    cudaEventCreateWithFlags(&evU[1], cudaEventDisableTiming);
    cudaEventCreateWithFlags(&evP0,   cudaEventDisableTiming);

    int prep_blocks = 2 + INIT_BLKS + (nE + 255) / 256;
    prep<<<prep_blocks, 256, 0, s1>>>(edge_row, nE, X, Xs, W1, W2, W3, Wl,
                                      hh0, hsA);
    cudaEventRecord(evFork, s1);
    cudaStreamWaitEvent(s2, evFork, 0);

    float* hsc = hsA; float* hsn = hsB;
    for (int d = 0; d < 3; d++) {
        __half* hhc = hhbuf[d % 3];
        __half* hhn = hhbuf[(d + 1) % 3];
        float*  hsout = (d == 2) ? (out + N_NODES * D_EMB) : hsn;
        int     mode  = (d == 2) ? 1 : 0;

        if (d == 0) {
            // host order: prep[2], pool_partial[3], pool_reduce[4], spmm[5]
            pool_partial<<<PB, 128, 0, s2>>>(hhc, batch_assign, N_NODES);
            cudaEventRecord(evP0, s2);
            pool_reduce<<<16, 256, 0, s2>>>();
            spmm<<<(N_NODES * 32 + 255) / 256, 256, 0, s1>>>(
                (const __half2*)hhc, edge_col, rp, (__half2*)hnv);
            update_hs<<<2, 128, 0, s2>>>(hsc, bl, hsout);
        } else {
            cudaStreamWaitEvent(s2, evU[d - 1], 0);   // pool reads h(d)
            spmm<<<(N_NODES * 32 + 255) / 256, 256, 0, s1>>>(
                (const __half2*)hhc, edge_col, rp, (__half2*)hnv);
            pool_partial<<<PB, 128, 0, s2>>>(hhc, batch_assign, N_NODES);
            pool_reduce<<<16, 256, 0, s2>>>();
            update_hs<<<2, 128, 0, s2>>>(hsc, bl, hsout);
        }

        // WAR: update_h(2) writes hh0, which pool_partial(0) read
        if (d == 2) cudaStreamWaitEvent(s1, evP0, 0);
        update_h<<<(NPAD / UH_NODES), 128, 0, s1>>>(
            hhc, hnv, Wt, bl, out, hhn, N_NODES, mode);
        if (d < 2) cudaEventRecord(evU[d], s1);

        float* tf = hsc; hsc = hsn; hsn = tf;
    }

    cudaEventRecord(evEnd, s2);
    cudaStreamWaitEvent(s1, evEnd, 0);   // join: all output visible on s1
}